// round 4
// baseline (speedup 1.0000x reference)
#include <cuda_runtime.h>
#include <math.h>

#define T_DIM 500
#define B_DIM 32
#define U_DIM 100
#define I_DIM 1024
#define E_DIM 512
#define M_DIM 512
#define C_DIM 1024
#define O_DIM 512
#define G_DIM 4096
#define NUM_CLASS 5000

// ---------------- scratch ----------------------------------------------------
__device__ float g_att_h[T_DIM * B_DIM * M_DIM];     // [t*32+b][m]
__device__ float g_emb[U_DIM * E_DIM * B_DIM];       // [u][e][b]
__device__ float g_gpart[8 * G_DIM * B_DIM];         // [ky][j][b]
__device__ float g_ppart[8 * O_DIM * B_DIM];         // [ky][r][b]
__device__ float g_c[C_DIM * B_DIM];
__device__ float g_h[C_DIM * B_DIM];
__device__ float g_p[O_DIM * B_DIM];                 // [r][b]
__device__ float g_state[B_DIM * M_DIM];             // [b][m]
__device__ float g_ctx[I_DIM * B_DIM];               // [i][b]
__device__ float g_scalar[T_DIM * B_DIM];            // [t][b]

__device__ __forceinline__ float fast_tanh(float x) {
    float y; asm("tanh.approx.f32 %0, %1;" : "=f"(y) : "f"(x)); return y;
}
__device__ __forceinline__ float sigf(float x) { return 1.0f / (1.0f + expf(-x)); }

// ---------------- embedding --------------------------------------------------
__global__ void k_embed(const int* __restrict__ label, const float* __restrict__ embW) {
    int idx = blockIdx.x * 256 + threadIdx.x;
    if (idx >= U_DIM * E_DIM * B_DIM) return;
    int b = idx & 31;
    int e = (idx >> 5) & (E_DIM - 1);
    int u = idx >> 14;
    int lab = (u == 0) ? (NUM_CLASS - 2) : label[(u - 1) * B_DIM + b];
    float v = 0.0f;
    if (lab >= 0) v = embW[lab * E_DIM + e];
    g_emb[idx] = v;
}

// ---------------- att_h = data @ Wi2h^T (16000 x 512 x 1024) -----------------
__global__ void k_atth(const float* __restrict__ data, const float* __restrict__ Wi2h) {
    __shared__ float As[16][64];
    __shared__ float Bs[16][64];
    int n0 = blockIdx.x * 64, m0 = blockIdx.y * 64;
    int tid = threadIdx.x;
    int tx = tid & 15, ty = tid >> 4;
    float acc[4][4];
#pragma unroll
    for (int i = 0; i < 4; i++)
#pragma unroll
        for (int j = 0; j < 4; j++) acc[i][j] = 0.0f;
    int kk = tid & 15, nn = tid >> 4;
    for (int k0 = 0; k0 < I_DIM; k0 += 16) {
#pragma unroll
        for (int r = 0; r < 4; r++)
            As[kk][nn + r * 16] = __ldcs(&data[(n0 + nn + r * 16) * I_DIM + k0 + kk]);
#pragma unroll
        for (int r = 0; r < 4; r++)
            Bs[kk][nn + r * 16] = Wi2h[(m0 + nn + r * 16) * I_DIM + k0 + kk];
        __syncthreads();
#pragma unroll
        for (int k = 0; k < 16; k++) {
            float4 a = *(const float4*)&As[k][ty * 4];
            float4 bv = *(const float4*)&Bs[k][tx * 4];
            acc[0][0] += a.x * bv.x; acc[0][1] += a.x * bv.y; acc[0][2] += a.x * bv.z; acc[0][3] += a.x * bv.w;
            acc[1][0] += a.y * bv.x; acc[1][1] += a.y * bv.y; acc[1][2] += a.y * bv.z; acc[1][3] += a.y * bv.w;
            acc[2][0] += a.z * bv.x; acc[2][1] += a.z * bv.y; acc[2][2] += a.z * bv.z; acc[2][3] += a.z * bv.w;
            acc[3][0] += a.w * bv.x; acc[3][1] += a.w * bv.y; acc[3][2] += a.w * bv.z; acc[3][3] += a.w * bv.w;
        }
        __syncthreads();
    }
#pragma unroll
    for (int i = 0; i < 4; i++)
#pragma unroll
        for (int j = 0; j < 4; j++)
            g_att_h[(n0 + ty * 4 + i) * M_DIM + m0 + tx * 4 + j] = acc[i][j];
}

__global__ void k_init() {
    int idx = blockIdx.x * 256 + threadIdx.x;
    if (idx < C_DIM * B_DIM) g_c[idx] = 0.0f;
    if (idx < O_DIM * B_DIM) g_p[idx] = 0.0f;
    if (idx < I_DIM * B_DIM) g_ctx[idx] = 0.0f;
}

// ---------------- gates partial GEMM: grid (64, 8), 64 rows x 256 k per block -
__global__ void k_gates(const float* __restrict__ Wx, const float* __restrict__ Wp, int u) {
    __shared__ float Wsm[64 * 64];       // [row][k]
    __shared__ float xsm[64 * 33];       // [k][b] padded
    int tid = threadIdx.x;
    int lane = tid & 31, w = tid >> 5;
    int ky = blockIdx.y;
    int row0 = blockIdx.x * 64;
    int kseg = ky * 256;

    const float* xsrc;
    if (kseg < 512)        xsrc = g_emb + u * (E_DIM * B_DIM) + kseg * 32;
    else if (kseg < 1536)  xsrc = g_ctx + (kseg - 512) * 32;
    else                   xsrc = g_p + (kseg - 1536) * 32;
    const float* wsrc; int wstride;
    if (ky < 6) { wsrc = Wx + kseg;          wstride = 1536; }
    else        { wsrc = Wp + (kseg - 1536); wstride = 512;  }

    float acc[8];
#pragma unroll
    for (int r = 0; r < 8; r++) acc[r] = 0.0f;

    float4 wr[4], xr[2];
    {
#pragma unroll
        for (int q = 0; q < 4; q++) {
            int idx = q * 256 + tid; int r = idx >> 4, c = (idx & 15) * 4;
            wr[q] = *(const float4*)&wsrc[(row0 + r) * wstride + c];
        }
#pragma unroll
        for (int q = 0; q < 2; q++) {
            int idx = q * 256 + tid; int k = idx >> 3, b = (idx & 7) * 4;
            xr[q] = *(const float4*)&xsrc[k * 32 + b];
        }
    }
    for (int sub = 0; sub < 4; sub++) {
        __syncthreads();
#pragma unroll
        for (int q = 0; q < 4; q++) {
            int idx = q * 256 + tid; int r = idx >> 4, c = (idx & 15) * 4;
            *(float4*)&Wsm[r * 64 + c] = wr[q];
        }
#pragma unroll
        for (int q = 0; q < 2; q++) {
            int idx = q * 256 + tid; int k = idx >> 3, b = (idx & 7) * 4;
            float4 v = xr[q]; int base = k * 33 + b;
            xsm[base] = v.x; xsm[base + 1] = v.y; xsm[base + 2] = v.z; xsm[base + 3] = v.w;
        }
        __syncthreads();
        if (sub < 3) {
            int k0 = (sub + 1) * 64;
#pragma unroll
            for (int q = 0; q < 4; q++) {
                int idx = q * 256 + tid; int r = idx >> 4, c = (idx & 15) * 4;
                wr[q] = *(const float4*)&wsrc[(row0 + r) * wstride + k0 + c];
            }
#pragma unroll
            for (int q = 0; q < 2; q++) {
                int idx = q * 256 + tid; int k = idx >> 3, b = (idx & 7) * 4;
                xr[q] = *(const float4*)&xsrc[(k0 + k) * 32 + b];
            }
        }
#pragma unroll 4
        for (int kk = 0; kk < 64; kk += 4) {
            float x0 = xsm[kk * 33 + lane];
            float x1 = xsm[(kk + 1) * 33 + lane];
            float x2 = xsm[(kk + 2) * 33 + lane];
            float x3 = xsm[(kk + 3) * 33 + lane];
#pragma unroll
            for (int r = 0; r < 8; r++) {
                float4 wv = *(const float4*)&Wsm[(w * 8 + r) * 64 + kk];
                acc[r] += wv.x * x0 + wv.y * x1 + wv.z * x2 + wv.w * x3;
            }
        }
    }
#pragma unroll
    for (int r = 0; r < 8; r++) {
        int j = row0 + w * 8 + r;
        g_gpart[ky * (G_DIM * 32) + j * 32 + lane] = acc[r];
    }
}

// ---------------- LSTM pointwise (+ 8-way gate partial reduction) ------------
__global__ void k_lstm(const float* __restrict__ bias) {
    int idx = blockIdx.x * 256 + threadIdx.x;  // ci*32+b
    int ci = idx >> 5, b = idx & 31;
    float gt[4];
#pragma unroll
    for (int gi = 0; gi < 4; gi++) {
        int j = gi * 1024 + ci;
        float s = bias[j];
#pragma unroll
        for (int ky = 0; ky < 8; ky++) s += g_gpart[ky * (G_DIM * 32) + j * 32 + b];
        gt[gi] = s;
    }
    float c = g_c[idx];
    c = sigf(gt[1]) * c + sigf(gt[0]) * tanhf(gt[2]);
    c = fminf(fmaxf(c, -1.0f), 1.0f);
    g_c[idx] = c;
    g_h[idx] = sigf(gt[3]) * tanhf(c);
}

// ---------------- proj partial GEMM: grid (8, 8), 64 rows x 128 k -------------
__global__ void k_proj(const float* __restrict__ Wproj) {
    __shared__ float Wsm[64 * 64];
    __shared__ float xsm[64 * 33];
    int tid = threadIdx.x;
    int lane = tid & 31, w = tid >> 5;
    int ky = blockIdx.y;
    int row0 = blockIdx.x * 64;
    const float* wsrc = Wproj + ky * 128;
    const float* xsrc = g_h + ky * 128 * 32;

    float acc[8];
#pragma unroll
    for (int r = 0; r < 8; r++) acc[r] = 0.0f;
    float4 wr[4], xr[2];
    {
#pragma unroll
        for (int q = 0; q < 4; q++) {
            int idx = q * 256 + tid; int r = idx >> 4, c = (idx & 15) * 4;
            wr[q] = *(const float4*)&wsrc[(row0 + r) * 1024 + c];
        }
#pragma unroll
        for (int q = 0; q < 2; q++) {
            int idx = q * 256 + tid; int k = idx >> 3, b = (idx & 7) * 4;
            xr[q] = *(const float4*)&xsrc[k * 32 + b];
        }
    }
    for (int sub = 0; sub < 2; sub++) {
        __syncthreads();
#pragma unroll
        for (int q = 0; q < 4; q++) {
            int idx = q * 256 + tid; int r = idx >> 4, c = (idx & 15) * 4;
            *(float4*)&Wsm[r * 64 + c] = wr[q];
        }
#pragma unroll
        for (int q = 0; q < 2; q++) {
            int idx = q * 256 + tid; int k = idx >> 3, b = (idx & 7) * 4;
            float4 v = xr[q]; int base = k * 33 + b;
            xsm[base] = v.x; xsm[base + 1] = v.y; xsm[base + 2] = v.z; xsm[base + 3] = v.w;
        }
        __syncthreads();
        if (sub < 1) {
#pragma unroll
            for (int q = 0; q < 4; q++) {
                int idx = q * 256 + tid; int r = idx >> 4, c = (idx & 15) * 4;
                wr[q] = *(const float4*)&wsrc[(row0 + r) * 1024 + 64 + c];
            }
#pragma unroll
            for (int q = 0; q < 2; q++) {
                int idx = q * 256 + tid; int k = idx >> 3, b = (idx & 7) * 4;
                xr[q] = *(const float4*)&xsrc[(64 + k) * 32 + b];
            }
        }
#pragma unroll 4
        for (int kk = 0; kk < 64; kk += 4) {
            float x0 = xsm[kk * 33 + lane];
            float x1 = xsm[(kk + 1) * 33 + lane];
            float x2 = xsm[(kk + 2) * 33 + lane];
            float x3 = xsm[(kk + 3) * 33 + lane];
#pragma unroll
            for (int r = 0; r < 8; r++) {
                float4 wv = *(const float4*)&Wsm[(w * 8 + r) * 64 + kk];
                acc[r] += wv.x * x0 + wv.y * x1 + wv.z * x2 + wv.w * x3;
            }
        }
    }
#pragma unroll
    for (int r = 0; r < 8; r++) {
        int j = row0 + w * 8 + r;
        g_ppart[ky * (O_DIM * 32) + j * 32 + lane] = acc[r];
    }
}

// ---------------- state = Wp2s @ p ; fused pfix: reduce ppart, write p + out --
// grid 8 blocks x 256 threads; dynamic smem: xsm[512*33] + Wsm[64*64]
__global__ void k_state(const float* __restrict__ Wp2s, const float* __restrict__ attm,
                        float* __restrict__ out, int u) {
    extern __shared__ float sm[];
    float* xsm = sm;                 // 512*33
    float* Wsm = sm + 512 * 33;      // 64*64
    int tid = threadIdx.x;
    int lane = tid & 31, w = tid >> 5;
    int row0 = blockIdx.x * 64;

    // stage full reduced p into smem; block 0 also writes g_p and masked lstmp out
#pragma unroll 2
    for (int q = 0; q < 16; q++) {
        int idx = q * 256 + tid; int k = idx >> 3, b = (idx & 7) * 4;
        float4 s = make_float4(0.f, 0.f, 0.f, 0.f);
#pragma unroll
        for (int ky = 0; ky < 8; ky++) {
            float4 v = *(const float4*)&g_ppart[ky * (O_DIM * 32) + k * 32 + b];
            s.x += v.x; s.y += v.y; s.z += v.z; s.w += v.w;
        }
        int base = k * 33 + b;
        xsm[base] = s.x; xsm[base + 1] = s.y; xsm[base + 2] = s.z; xsm[base + 3] = s.w;
        if (blockIdx.x == 0) {
            *(float4*)&g_p[k * 32 + b] = s;
            float m0 = attm[u * 32 + b + 0], m1 = attm[u * 32 + b + 1];
            float m2 = attm[u * 32 + b + 2], m3 = attm[u * 32 + b + 3];
            out[u * (B_DIM * 1536) + (b + 0) * 1536 + k] = s.x * m0;
            out[u * (B_DIM * 1536) + (b + 1) * 1536 + k] = s.y * m1;
            out[u * (B_DIM * 1536) + (b + 2) * 1536 + k] = s.z * m2;
            out[u * (B_DIM * 1536) + (b + 3) * 1536 + k] = s.w * m3;
        }
    }
    __syncthreads();

    float acc[8];
#pragma unroll
    for (int r = 0; r < 8; r++) acc[r] = 0.0f;
    for (int sub = 0; sub < 8; sub++) {
#pragma unroll
        for (int q = 0; q < 4; q++) {
            int idx = q * 256 + tid; int r = idx >> 4, c = (idx & 15) * 4;
            *(float4*)&Wsm[r * 64 + c] = *(const float4*)&Wp2s[(row0 + r) * 512 + sub * 64 + c];
        }
        __syncthreads();
#pragma unroll 4
        for (int kk = 0; kk < 64; kk += 4) {
            int kb = sub * 64 + kk;
            float x0 = xsm[kb * 33 + lane];
            float x1 = xsm[(kb + 1) * 33 + lane];
            float x2 = xsm[(kb + 2) * 33 + lane];
            float x3 = xsm[(kb + 3) * 33 + lane];
#pragma unroll
            for (int r = 0; r < 8; r++) {
                float4 wv = *(const float4*)&Wsm[(w * 8 + r) * 64 + kk];
                acc[r] += wv.x * x0 + wv.y * x1 + wv.z * x2 + wv.w * x3;
            }
        }
        __syncthreads();
    }
#pragma unroll
    for (int r = 0; r < 8; r++) {
        int m = row0 + w * 8 + r;
        g_state[lane * 512 + m] = acc[r];   // [b][m]
    }
}

// ---------------- attention scalars: one block per t --------------------------
__global__ void k_scalar(const float* __restrict__ rnn_mask, const float* __restrict__ wv) {
    __shared__ float wvs[512];
    int tid = threadIdx.x;
    int lane = tid & 31, w = tid >> 5;   // w in 0..15
    if (tid < 512) wvs[tid] = wv[tid];
    __syncthreads();
    int t = blockIdx.x;
#pragma unroll
    for (int rep = 0; rep < 2; rep++) {
        int b = w + rep * 16;
        const float* ah = g_att_h + (t * 32 + b) * 512;
        const float* st = g_state + b * 512;
        float s = 0.0f;
#pragma unroll
        for (int it = 0; it < 16; it++) {
            int m = lane + it * 32;
            s += wvs[m] * fast_tanh(st[m] + ah[m]);
        }
#pragma unroll
        for (int off = 16; off; off >>= 1) s += __shfl_xor_sync(0xffffffffu, s, off);
        if (lane == 0) {
            float bv = (rnn_mask[t * 32 + b] - 1.0f) * 1e10f;
            g_scalar[t * 32 + b] = 1.0f / (1.0f + __expf(-(s + bv)));
        }
    }
}

// ---------------- ctx: single-stage sweep over all T, fused output write ------
__global__ void k_ctx(const float* __restrict__ data, const float* __restrict__ attm,
                      float* __restrict__ out, int u) {
    __shared__ float ssm[T_DIM];
    int tid = threadIdx.x;
    int idx = blockIdx.x * 256 + tid;          // b*1024 + i
    int b = idx >> 10;
    for (int s = tid; s < T_DIM; s += 256) ssm[s] = g_scalar[s * 32 + b];
    __syncthreads();
    float a0 = 0.f, a1 = 0.f, a2 = 0.f, a3 = 0.f;
    for (int t0 = 0; t0 < T_DIM; t0 += 20) {
        float d[20];
#pragma unroll
        for (int j = 0; j < 20; j++) d[j] = __ldcs(&data[(t0 + j) * (B_DIM * I_DIM) + idx]);
#pragma unroll
        for (int j = 0; j < 20; j += 4) {
            a0 += d[j + 0] * ssm[t0 + j + 0];
            a1 += d[j + 1] * ssm[t0 + j + 1];
            a2 += d[j + 2] * ssm[t0 + j + 2];
            a3 += d[j + 3] * ssm[t0 + j + 3];
        }
    }
    float s = (a0 + a1) + (a2 + a3);
    int i = idx & 1023;
    g_ctx[i * 32 + b] = s;
    out[u * (B_DIM * 1536) + b * 1536 + 512 + i] = s * attm[u * 32 + b];
}

// ---------------- launch -------------------------------------------------------
extern "C" void kernel_launch(void* const* d_in, const int* in_sizes, int n_in,
                              void* d_out, int out_size) {
    const float* data      = (const float*)d_in[0];
    const float* att_mask  = (const float*)d_in[1];
    const int*   att_label = (const int*)  d_in[2];
    const float* rnn_mask  = (const float*)d_in[3];
    const float* embW      = (const float*)d_in[4];
    const float* Wi2h      = (const float*)d_in[5];
    const float* Wp2s      = (const float*)d_in[6];
    const float* wv        = (const float*)d_in[7];
    const float* Wx        = (const float*)d_in[8];
    const float* Wp        = (const float*)d_in[9];
    const float* bias      = (const float*)d_in[10];
    const float* Wproj     = (const float*)d_in[11];
    float* out = (float*)d_out;

    static int smem_set = 0;
    if (!smem_set) {
        cudaFuncSetAttribute(k_state, cudaFuncAttributeMaxDynamicSharedMemorySize,
                             (512 * 33 + 64 * 64) * 4);
        smem_set = 1;
    }

    k_embed<<<6400, 256>>>(att_label, embW);
    dim3 gg(250, 8);
    k_atth<<<gg, 256>>>(data, Wi2h);
    k_init<<<128, 256>>>();

    for (int u = 0; u < U_DIM; u++) {
        k_gates<<<dim3(64, 8), 256>>>(Wx, Wp, u);
        k_lstm<<<128, 256>>>(bias);
        k_proj<<<dim3(8, 8), 256>>>(Wproj);
        k_state<<<8, 256, (512 * 33 + 64 * 64) * 4>>>(Wp2s, att_mask, out, u);
        k_scalar<<<500, 512>>>(rnn_mask, wv);
        k_ctx<<<128, 256>>>(data, att_mask, out, u);
    }
}

// round 5
// speedup vs baseline: 1.2623x; 1.2623x over previous
#include <cuda_runtime.h>
#include <math.h>
#include <stdint.h>

#define T_DIM 500
#define B_DIM 32
#define U_DIM 100
#define I_DIM 1024
#define E_DIM 512
#define M_DIM 512
#define C_DIM 1024
#define O_DIM 512
#define G_DIM 4096
#define NUM_CLASS 5000

// ---------------- scratch (device globals) -----------------------------------
__device__ __align__(16) uint32_t g_wt[G_DIM / 16 * 2048 / 8 * 32 * 4];   // 33.5MB packed W frags
__device__ __align__(16) uint32_t g_dt[16000 / 16 * 1024 / 8 * 32 * 4];  // 65.5MB packed data frags
__device__ __align__(16) uint32_t g_bt[1024 / 8 * 512 / 8 * 32 * 2];     // 2MB packed Wi2h frags
__device__ __align__(16) uint32_t g_xemb[U_DIM * 64 * 4 * 32 * 2];       // packed emb frags per u
__device__ __align__(16) uint32_t g_xt[256 * 4 * 32 * 2];                // packed x frags (ctx+p region)
__device__ float g_att_h[T_DIM * B_DIM * M_DIM];     // [t*32+b][m]
__device__ float g_gpart[4 * G_DIM * B_DIM];         // [ky][j][b]
__device__ float g_ppart[8 * O_DIM * B_DIM];         // [ky][r][b]
__device__ float g_c[C_DIM * B_DIM];
__device__ float g_h[C_DIM * B_DIM];
__device__ float g_state[B_DIM * M_DIM];             // [b][m]
__device__ float g_scalar[T_DIM * B_DIM];            // [t][b]
__device__ float g_cpart[5 * B_DIM * I_DIM];         // [chunk][b*1024+i]

__device__ __forceinline__ float fast_tanh(float x) {
    float y; asm("tanh.approx.f32 %0, %1;" : "=f"(y) : "f"(x)); return y;
}
__device__ __forceinline__ float sigf(float x) { return 1.0f / (1.0f + expf(-x)); }
__device__ __forceinline__ uint32_t f2tf(float v) {
    uint32_t r; asm("cvt.rna.tf32.f32 %0, %1;" : "=r"(r) : "f"(v)); return r;
}
__device__ __forceinline__ void mma8(float& d0, float& d1, float& d2, float& d3,
                                     uint32_t a0, uint32_t a1, uint32_t a2, uint32_t a3,
                                     uint32_t b0, uint32_t b1) {
    asm("mma.sync.aligned.m16n8k8.row.col.f32.tf32.tf32.f32 "
        "{%0,%1,%2,%3},{%4,%5,%6,%7},{%8,%9},{%0,%1,%2,%3};"
        : "+f"(d0), "+f"(d1), "+f"(d2), "+f"(d3)
        : "r"(a0), "r"(a1), "r"(a2), "r"(a3), "r"(b0), "r"(b1));
}

// ---------------- pack W = [Wx | Wp] into A-fragment layout -------------------
// idx = ((mt*256 + kt)*32 + lane)*4 + r ; row+= (r&1)*8, col += (r>>1)*4
__global__ void k_wpack(const float* __restrict__ Wx, const float* __restrict__ Wp) {
    int idx = blockIdx.x * 256 + threadIdx.x;        // 8,388,608
    int r = idx & 3, lane = (idx >> 2) & 31, kt = (idx >> 7) & 255, mt = idx >> 15;
    int j = mt * 16 + (lane >> 2) + (r & 1) * 8;
    int k = kt * 8 + (lane & 3) + (r >> 1) * 4;
    float v = (k < 1536) ? Wx[j * 1536 + k] : Wp[j * 512 + (k - 1536)];
    g_wt[idx] = f2tf(v);
}

// ---------------- pack data into A-fragment layout ----------------------------
// idx = ((mt*128 + kt)*32 + lane)*4 + r
__global__ void k_dpack(const float* __restrict__ data) {
    int idx = blockIdx.x * 256 + threadIdx.x;        // 16,384,000
    int r = idx & 3, lane = (idx >> 2) & 31, kt = (idx >> 7) & 127, mt = idx >> 14;
    int m = mt * 16 + (lane >> 2) + (r & 1) * 8;
    int k = kt * 8 + (lane & 3) + (r >> 1) * 4;
    g_dt[idx] = f2tf(data[m * 1024 + k]);
}

// ---------------- pack Wi2h into B-fragment layout ----------------------------
// idx = ((kt*64 + nt)*32 + lane)*2 + r ; B[k][n] = Wi2h[n][k]
__global__ void k_bpack(const float* __restrict__ Wi2h) {
    int idx = blockIdx.x * 256 + threadIdx.x;        // 524,288
    int r = idx & 1, lane = (idx >> 1) & 31, nt = (idx >> 6) & 63, kt = idx >> 12;
    int k = kt * 8 + (lane & 3) + r * 4;
    int n = nt * 8 + (lane >> 2);
    g_bt[idx] = f2tf(Wi2h[n * 1024 + k]);
}

// ---------------- embedding -> packed B fragments per u ------------------------
// idx = (((u*64 + kt)*4 + nt)*32 + lane)*2 + r
__global__ void k_embed(const int* __restrict__ label, const float* __restrict__ embW) {
    int idx = blockIdx.x * 256 + threadIdx.x;        // 1,638,400
    int r = idx & 1, lane = (idx >> 1) & 31, nt = (idx >> 6) & 3, kt = (idx >> 8) & 63, u = idx >> 14;
    int e = kt * 8 + (lane & 3) + r * 4;
    int b = nt * 8 + (lane >> 2);
    int lab = (u == 0) ? (NUM_CLASS - 2) : label[(u - 1) * B_DIM + b];
    float v = 0.0f;
    if (lab >= 0) v = embW[lab * E_DIM + e];
    g_xemb[idx] = f2tf(v);
}

// ---------------- init: zero c and packed x (ctx=0, p=0) ----------------------
__global__ void k_init() {
    int idx = blockIdx.x * 256 + threadIdx.x;        // 65536
    if (idx < C_DIM * B_DIM) g_c[idx] = 0.0f;
    if (idx < 65536) g_xt[idx] = 0u;                 // tf32(0) == 0
}

// ---------------- att_h via tf32 mma: block m128 x n128, 512 thr --------------
__global__ void __launch_bounds__(512) k_atth(void) {
    int tid = threadIdx.x;
    int lane = tid & 31, wid = tid >> 5;
    int wm = wid & 7, wn = wid >> 3;
    int mt = blockIdx.x * 8 + wm;                    // global m-tile (0..999)
    int ntb = blockIdx.y * 16 + wn * 8;              // base n-tile (0..63)

    float d[8][4];
#pragma unroll
    for (int n = 0; n < 8; n++)
#pragma unroll
        for (int c = 0; c < 4; c++) d[n][c] = 0.0f;

    const uint4* ap = reinterpret_cast<const uint4*>(g_dt) + (mt * 128) * 32 + lane;
    const uint2* bp = reinterpret_cast<const uint2*>(g_bt) + ntb * 32 + lane;
#pragma unroll 2
    for (int kt = 0; kt < 128; kt++) {
        uint4 a = ap[kt * 32];
#pragma unroll
        for (int n = 0; n < 8; n++) {
            uint2 b = bp[(kt * 64 + n) * 32];
            mma8(d[n][0], d[n][1], d[n][2], d[n][3], a.x, a.y, a.z, a.w, b.x, b.y);
        }
    }
    int gid = lane >> 2, tig = lane & 3;
    int m0 = mt * 16 + gid;
#pragma unroll
    for (int n = 0; n < 8; n++) {
        int nn = (ntb + n) * 8 + 2 * tig;
        *(float2*)&g_att_h[m0 * 512 + nn]       = make_float2(d[n][0], d[n][1]);
        *(float2*)&g_att_h[(m0 + 8) * 512 + nn] = make_float2(d[n][2], d[n][3]);
    }
}

// ---------------- gates via tf32 mma: grid (32, 4), 256 thr -------------------
// block = 128 rows x 32 batch x 512 k ; warp = m16 x n32
__global__ void k_gates(int u) {
    int tid = threadIdx.x;
    int lane = tid & 31, wid = tid >> 5;
    int ky = blockIdx.y;
    int mt = blockIdx.x * 8 + wid;                   // global m-tile (0..255)

    const uint2* bsrc = (ky == 0)
        ? reinterpret_cast<const uint2*>(g_xemb) + u * 8192
        : reinterpret_cast<const uint2*>(g_xt) + ky * 8192;

    float d[4][4];
#pragma unroll
    for (int n = 0; n < 4; n++)
#pragma unroll
        for (int c = 0; c < 4; c++) d[n][c] = 0.0f;

    const uint4* ap = reinterpret_cast<const uint4*>(g_wt) + (mt * 256 + ky * 64) * 32 + lane;
#pragma unroll 4
    for (int kt = 0; kt < 64; kt++) {
        uint4 a = ap[kt * 32];
#pragma unroll
        for (int n = 0; n < 4; n++) {
            uint2 b = bsrc[(kt * 4 + n) * 32 + lane];
            mma8(d[n][0], d[n][1], d[n][2], d[n][3], a.x, a.y, a.z, a.w, b.x, b.y);
        }
    }
    int gid = lane >> 2, tig = lane & 3;
    int j0 = mt * 16 + gid;
    float* gp = g_gpart + ky * (G_DIM * 32);
#pragma unroll
    for (int n = 0; n < 4; n++) {
        int bb = n * 8 + 2 * tig;
        *(float2*)&gp[j0 * 32 + bb]       = make_float2(d[n][0], d[n][1]);
        *(float2*)&gp[(j0 + 8) * 32 + bb] = make_float2(d[n][2], d[n][3]);
    }
}

// ---------------- LSTM pointwise (+ 4-way gate partial reduction) -------------
__global__ void k_lstm(const float* __restrict__ bias) {
    int idx = blockIdx.x * 256 + threadIdx.x;  // ci*32+b
    int ci = idx >> 5, b = idx & 31;
    float gt[4];
#pragma unroll
    for (int gi = 0; gi < 4; gi++) {
        int j = gi * 1024 + ci;
        float s = bias[j];
#pragma unroll
        for (int ky = 0; ky < 4; ky++) s += g_gpart[ky * (G_DIM * 32) + j * 32 + b];
        gt[gi] = s;
    }
    float c = g_c[idx];
    c = sigf(gt[1]) * c + sigf(gt[0]) * tanhf(gt[2]);
    c = fminf(fmaxf(c, -1.0f), 1.0f);
    g_c[idx] = c;
    g_h[idx] = sigf(gt[3]) * tanhf(c);
}

// ---------------- proj partial GEMM (fp32): grid (8, 8), 64 rows x 128 k ------
__global__ void k_proj(const float* __restrict__ Wproj) {
    __shared__ float Wsm[64 * 64];
    __shared__ float xsm[64 * 33];
    int tid = threadIdx.x;
    int lane = tid & 31, w = tid >> 5;
    int ky = blockIdx.y;
    int row0 = blockIdx.x * 64;
    const float* wsrc = Wproj + ky * 128;
    const float* xsrc = g_h + ky * 128 * 32;

    float acc[8];
#pragma unroll
    for (int r = 0; r < 8; r++) acc[r] = 0.0f;
    float4 wr[4], xr[2];
    {
#pragma unroll
        for (int q = 0; q < 4; q++) {
            int idx = q * 256 + tid; int r = idx >> 4, c = (idx & 15) * 4;
            wr[q] = *(const float4*)&wsrc[(row0 + r) * 1024 + c];
        }
#pragma unroll
        for (int q = 0; q < 2; q++) {
            int idx = q * 256 + tid; int k = idx >> 3, b = (idx & 7) * 4;
            xr[q] = *(const float4*)&xsrc[k * 32 + b];
        }
    }
    for (int sub = 0; sub < 2; sub++) {
        __syncthreads();
#pragma unroll
        for (int q = 0; q < 4; q++) {
            int idx = q * 256 + tid; int r = idx >> 4, c = (idx & 15) * 4;
            *(float4*)&Wsm[r * 64 + c] = wr[q];
        }
#pragma unroll
        for (int q = 0; q < 2; q++) {
            int idx = q * 256 + tid; int k = idx >> 3, b = (idx & 7) * 4;
            float4 v = xr[q]; int base = k * 33 + b;
            xsm[base] = v.x; xsm[base + 1] = v.y; xsm[base + 2] = v.z; xsm[base + 3] = v.w;
        }
        __syncthreads();
        if (sub < 1) {
#pragma unroll
            for (int q = 0; q < 4; q++) {
                int idx = q * 256 + tid; int r = idx >> 4, c = (idx & 15) * 4;
                wr[q] = *(const float4*)&wsrc[(row0 + r) * 1024 + 64 + c];
            }
#pragma unroll
            for (int q = 0; q < 2; q++) {
                int idx = q * 256 + tid; int k = idx >> 3, b = (idx & 7) * 4;
                xr[q] = *(const float4*)&xsrc[(64 + k) * 32 + b];
            }
        }
#pragma unroll 4
        for (int kk = 0; kk < 64; kk += 4) {
            float x0 = xsm[kk * 33 + lane];
            float x1 = xsm[(kk + 1) * 33 + lane];
            float x2 = xsm[(kk + 2) * 33 + lane];
            float x3 = xsm[(kk + 3) * 33 + lane];
#pragma unroll
            for (int r = 0; r < 8; r++) {
                float4 wv = *(const float4*)&Wsm[(w * 8 + r) * 64 + kk];
                acc[r] += wv.x * x0 + wv.y * x1 + wv.z * x2 + wv.w * x3;
            }
        }
    }
#pragma unroll
    for (int r = 0; r < 8; r++) {
        int j = row0 + w * 8 + r;
        g_ppart[ky * (O_DIM * 32) + j * 32 + lane] = acc[r];
    }
}

// ---------------- state = Wp2s @ p; fused: reduce ppart, write packed p + out --
__global__ void k_state(const float* __restrict__ Wp2s, const float* __restrict__ attm,
                        float* __restrict__ out, int u) {
    extern __shared__ float sm[];
    float* xsm = sm;                 // 512*33
    float* Wsm = sm + 512 * 33;      // 64*64
    int tid = threadIdx.x;
    int lane = tid & 31, w = tid >> 5;
    int row0 = blockIdx.x * 64;

#pragma unroll 2
    for (int q = 0; q < 16; q++) {
        int idx = q * 256 + tid; int k = idx >> 3, b = (idx & 7) * 4;
        float4 s = make_float4(0.f, 0.f, 0.f, 0.f);
#pragma unroll
        for (int ky = 0; ky < 8; ky++) {
            float4 v = *(const float4*)&g_ppart[ky * (O_DIM * 32) + k * 32 + b];
            s.x += v.x; s.y += v.y; s.z += v.z; s.w += v.w;
        }
        int base = k * 33 + b;
        xsm[base] = s.x; xsm[base + 1] = s.y; xsm[base + 2] = s.z; xsm[base + 3] = s.w;
        if (blockIdx.x == 0) {
            float sv[4] = {s.x, s.y, s.z, s.w};
            int kt = 192 + (k >> 3);
            int reg = (k >> 2) & 1;
#pragma unroll
            for (int jj = 0; jj < 4; jj++) {
                int bb = b + jj;
                int ln = (bb & 7) * 4 + (k & 3);
                g_xt[((kt * 4 + (bb >> 3)) * 32 + ln) * 2 + reg] = f2tf(sv[jj]);
                out[u * (B_DIM * 1536) + bb * 1536 + k] = sv[jj] * attm[u * 32 + bb];
            }
        }
    }
    __syncthreads();

    float acc[8];
#pragma unroll
    for (int r = 0; r < 8; r++) acc[r] = 0.0f;
    for (int sub = 0; sub < 8; sub++) {
#pragma unroll
        for (int q = 0; q < 4; q++) {
            int idx = q * 256 + tid; int r = idx >> 4, c = (idx & 15) * 4;
            *(float4*)&Wsm[r * 64 + c] = *(const float4*)&Wp2s[(row0 + r) * 512 + sub * 64 + c];
        }
        __syncthreads();
#pragma unroll 4
        for (int kk = 0; kk < 64; kk += 4) {
            int kb = sub * 64 + kk;
            float x0 = xsm[kb * 33 + lane];
            float x1 = xsm[(kb + 1) * 33 + lane];
            float x2 = xsm[(kb + 2) * 33 + lane];
            float x3 = xsm[(kb + 3) * 33 + lane];
#pragma unroll
            for (int r = 0; r < 8; r++) {
                float4 wv = *(const float4*)&Wsm[(w * 8 + r) * 64 + kk];
                acc[r] += wv.x * x0 + wv.y * x1 + wv.z * x2 + wv.w * x3;
            }
        }
        __syncthreads();
    }
#pragma unroll
    for (int r = 0; r < 8; r++) {
        int m = row0 + w * 8 + r;
        g_state[lane * 512 + m] = acc[r];   // [b][m]
    }
}

// ---------------- attention scalars: one block per t --------------------------
__global__ void k_scalar(const float* __restrict__ rnn_mask, const float* __restrict__ wv) {
    __shared__ float wvs[512];
    int tid = threadIdx.x;
    int lane = tid & 31, w = tid >> 5;   // w in 0..15
    if (tid < 512) wvs[tid] = wv[tid];
    __syncthreads();
    int t = blockIdx.x;
#pragma unroll
    for (int rep = 0; rep < 2; rep++) {
        int b = w + rep * 16;
        const float* ah = g_att_h + (t * 32 + b) * 512;
        const float* st = g_state + b * 512;
        float s = 0.0f;
#pragma unroll
        for (int it = 0; it < 16; it++) {
            int m = lane + it * 32;
            s += wvs[m] * fast_tanh(st[m] + ah[m]);
        }
#pragma unroll
        for (int off = 16; off; off >>= 1) s += __shfl_xor_sync(0xffffffffu, s, off);
        if (lane == 0) {
            float bv = (rnn_mask[t * 32 + b] - 1.0f) * 1e10f;
            g_scalar[t * 32 + b] = 1.0f / (1.0f + __expf(-(s + bv)));
        }
    }
}

// ---------------- ctx partials: grid (128, 5) ---------------------------------
__global__ void k_ctx(const float* __restrict__ data) {
    __shared__ float ssm[100];
    int tid = threadIdx.x;
    int t0 = blockIdx.y * 100;
    int idx = blockIdx.x * 256 + tid;          // b*1024 + i
    int b = blockIdx.x >> 2;
    if (tid < 100) ssm[tid] = g_scalar[(t0 + tid) * 32 + b];
    __syncthreads();
    float a0 = 0.0f, a1 = 0.0f;
#pragma unroll 2
    for (int tt = 0; tt < 100; tt += 4) {
        a0 += __ldcs(&data[(t0 + tt + 0) * 32768 + idx]) * ssm[tt + 0];
        a1 += __ldcs(&data[(t0 + tt + 1) * 32768 + idx]) * ssm[tt + 1];
        a0 += __ldcs(&data[(t0 + tt + 2) * 32768 + idx]) * ssm[tt + 2];
        a1 += __ldcs(&data[(t0 + tt + 3) * 32768 + idx]) * ssm[tt + 3];
    }
    g_cpart[blockIdx.y * 32768 + idx] = a0 + a1;
}

// ---------------- reduce ctx partials -> packed ctx frags + masked out --------
__global__ void k_reduce(const float* __restrict__ attm, float* __restrict__ out, int u) {
    int idx = blockIdx.x * 256 + threadIdx.x;   // b*1024 + i
    float s = 0.0f;
#pragma unroll
    for (int p = 0; p < 5; p++) s += g_cpart[p * 32768 + idx];
    int b = idx >> 10, i = idx & 1023;
    int kt = 64 + (i >> 3);
    int ln = (b & 7) * 4 + (i & 3);
    int reg = (i >> 2) & 1;
    g_xt[((kt * 4 + (b >> 3)) * 32 + ln) * 2 + reg] = f2tf(s);
    out[u * (B_DIM * 1536) + b * 1536 + 512 + i] = s * attm[u * 32 + b];
}

// ---------------- launch -------------------------------------------------------
extern "C" void kernel_launch(void* const* d_in, const int* in_sizes, int n_in,
                              void* d_out, int out_size) {
    const float* data      = (const float*)d_in[0];
    const float* att_mask  = (const float*)d_in[1];
    const int*   att_label = (const int*)  d_in[2];
    const float* rnn_mask  = (const float*)d_in[3];
    const float* embW      = (const float*)d_in[4];
    const float* Wi2h      = (const float*)d_in[5];
    const float* Wp2s      = (const float*)d_in[6];
    const float* wv        = (const float*)d_in[7];
    const float* Wx        = (const float*)d_in[8];
    const float* Wp        = (const float*)d_in[9];
    const float* bias      = (const float*)d_in[10];
    const float* Wproj     = (const float*)d_in[11];
    float* out = (float*)d_out;

    cudaFuncSetAttribute(k_state, cudaFuncAttributeMaxDynamicSharedMemorySize,
                         (512 * 33 + 64 * 64) * 4);

    k_wpack<<<32768, 256>>>(Wx, Wp);
    k_dpack<<<64000, 256>>>(data);
    k_bpack<<<2048, 256>>>(Wi2h);
    k_embed<<<6400, 256>>>(att_label, embW);
    k_atth<<<dim3(125, 4), 512>>>();
    k_init<<<256, 256>>>();

    for (int u = 0; u < U_DIM; u++) {
        k_gates<<<dim3(32, 4), 256>>>(u);
        k_lstm<<<128, 256>>>(bias);
        k_proj<<<dim3(8, 8), 256>>>(Wproj);
        k_state<<<8, 256, (512 * 33 + 64 * 64) * 4>>>(Wp2s, att_mask, out, u);
        k_scalar<<<500, 512>>>(rnn_mask, wv);
        k_ctx<<<dim3(128, 5), 256>>>(data);
        k_reduce<<<128, 256>>>(att_mask, out, u);
    }
}

// round 8
// speedup vs baseline: 1.3824x; 1.0951x over previous
#include <cuda_runtime.h>
#include <math.h>
#include <stdint.h>

#define T_DIM 500
#define B_DIM 32
#define U_DIM 100
#define I_DIM 1024
#define E_DIM 512
#define M_DIM 512
#define C_DIM 1024
#define O_DIM 512
#define G_DIM 4096
#define NUM_CLASS 5000

// ---------------- scratch (device globals) -----------------------------------
__device__ __align__(16) uint32_t g_wt[G_DIM / 16 * 2048 / 8 * 32 * 4];  // packed W frags
__device__ __align__(16) uint32_t g_dt[16000 / 16 * 1024 / 8 * 32 * 4]; // packed data frags
__device__ __align__(16) uint32_t g_bt[1024 / 8 * 512 / 8 * 32 * 2];    // packed Wi2h frags
__device__ __align__(16) uint32_t g_xemb[U_DIM * 64 * 4 * 32 * 2];      // packed emb frags
__device__ __align__(16) uint32_t g_xt[256 * 4 * 32 * 2];               // packed x frags (ctx+p)
__device__ float g_att_h[T_DIM * B_DIM * M_DIM];     // [t*32+b][m]
__device__ float g_gpart[4 * G_DIM * B_DIM];         // [ky][j][b]
__device__ float g_ppart[8 * O_DIM * B_DIM];         // [ky][r][b]
__device__ float g_c[2][C_DIM * B_DIM];              // double-buffered cell state
__device__ float g_state[B_DIM * M_DIM];             // [b][m]
__device__ float g_scalar[T_DIM * B_DIM];            // [t][b]
__device__ float g_cpart[5 * B_DIM * I_DIM];         // [chunk][b*1024+i]
__device__ int   g_ctr[128];                          // ctx-reduce counters

__device__ __forceinline__ float fast_tanh(float x) {
    float y; asm("tanh.approx.f32 %0, %1;" : "=f"(y) : "f"(x)); return y;
}
__device__ __forceinline__ float sigf(float x) { return 1.0f / (1.0f + expf(-x)); }
__device__ __forceinline__ uint32_t f2tf(float v) {
    uint32_t r; asm("cvt.rna.tf32.f32 %0, %1;" : "=r"(r) : "f"(v)); return r;
}
__device__ __forceinline__ void mma8(float& d0, float& d1, float& d2, float& d3,
                                     uint32_t a0, uint32_t a1, uint32_t a2, uint32_t a3,
                                     uint32_t b0, uint32_t b1) {
    asm("mma.sync.aligned.m16n8k8.row.col.f32.tf32.tf32.f32 "
        "{%0,%1,%2,%3},{%4,%5,%6,%7},{%8,%9},{%0,%1,%2,%3};"
        : "+f"(d0), "+f"(d1), "+f"(d2), "+f"(d3)
        : "r"(a0), "r"(a1), "r"(a2), "r"(a3), "r"(b0), "r"(b1));
}

// ---------------- pack W = [Wx | Wp] into A-fragment layout -------------------
__global__ void k_wpack(const float* __restrict__ Wx, const float* __restrict__ Wp) {
    int idx = blockIdx.x * 256 + threadIdx.x;        // 8,388,608
    int r = idx & 3, lane = (idx >> 2) & 31, kt = (idx >> 7) & 255, mt = idx >> 15;
    int j = mt * 16 + (lane >> 2) + (r & 1) * 8;
    int k = kt * 8 + (lane & 3) + (r >> 1) * 4;
    float v = (k < 1536) ? Wx[j * 1536 + k] : Wp[j * 512 + (k - 1536)];
    g_wt[idx] = f2tf(v);
}

// ---------------- pack data into A-fragment layout ----------------------------
__global__ void k_dpack(const float* __restrict__ data) {
    int idx = blockIdx.x * 256 + threadIdx.x;        // 16,384,000
    int r = idx & 3, lane = (idx >> 2) & 31, kt = (idx >> 7) & 127, mt = idx >> 14;
    int m = mt * 16 + (lane >> 2) + (r & 1) * 8;
    int k = kt * 8 + (lane & 3) + (r >> 1) * 4;
    g_dt[idx] = f2tf(data[m * 1024 + k]);
}

// ---------------- pack Wi2h into B-fragment layout ----------------------------
__global__ void k_bpack(const float* __restrict__ Wi2h) {
    int idx = blockIdx.x * 256 + threadIdx.x;        // 524,288
    int r = idx & 1, lane = (idx >> 1) & 31, nt = (idx >> 6) & 63, kt = idx >> 12;
    int k = kt * 8 + (lane & 3) + r * 4;
    int n = nt * 8 + (lane >> 2);
    g_bt[idx] = f2tf(Wi2h[n * 1024 + k]);
}

// ---------------- embedding -> packed B fragments per u ------------------------
__global__ void k_embed(const int* __restrict__ label, const float* __restrict__ embW) {
    int idx = blockIdx.x * 256 + threadIdx.x;        // 1,638,400
    int r = idx & 1, lane = (idx >> 1) & 31, nt = (idx >> 6) & 3, kt = (idx >> 8) & 63, u = idx >> 14;
    int e = kt * 8 + (lane & 3) + r * 4;
    int b = nt * 8 + (lane >> 2);
    int lab = (u == 0) ? (NUM_CLASS - 2) : label[(u - 1) * B_DIM + b];
    float v = 0.0f;
    if (lab >= 0) v = embW[lab * E_DIM + e];
    g_xemb[idx] = f2tf(v);
}

// ---------------- init: zero c buf0 and packed x -------------------------------
__global__ void k_init() {
    int idx = blockIdx.x * 256 + threadIdx.x;        // 65536
    if (idx < C_DIM * B_DIM) g_c[0][idx] = 0.0f;
    if (idx < 65536) g_xt[idx] = 0u;
}

// ---------------- att_h via tf32 mma -------------------------------------------
__global__ void __launch_bounds__(512) k_atth(void) {
    int tid = threadIdx.x;
    int lane = tid & 31, wid = tid >> 5;
    int wm = wid & 7, wn = wid >> 3;
    int mt = blockIdx.x * 8 + wm;
    int ntb = blockIdx.y * 16 + wn * 8;

    float d[8][4];
#pragma unroll
    for (int n = 0; n < 8; n++)
#pragma unroll
        for (int c = 0; c < 4; c++) d[n][c] = 0.0f;

    const uint4* ap = reinterpret_cast<const uint4*>(g_dt) + (mt * 128) * 32 + lane;
    const uint2* bp = reinterpret_cast<const uint2*>(g_bt) + ntb * 32 + lane;
#pragma unroll 2
    for (int kt = 0; kt < 128; kt++) {
        uint4 a = ap[kt * 32];
#pragma unroll
        for (int n = 0; n < 8; n++) {
            uint2 b = bp[(kt * 64 + n) * 32];
            mma8(d[n][0], d[n][1], d[n][2], d[n][3], a.x, a.y, a.z, a.w, b.x, b.y);
        }
    }
    int gid = lane >> 2, tig = lane & 3;
    int m0 = mt * 16 + gid;
#pragma unroll
    for (int n = 0; n < 8; n++) {
        int nn = (ntb + n) * 8 + 2 * tig;
        *(float2*)&g_att_h[m0 * 512 + nn]       = make_float2(d[n][0], d[n][1]);
        *(float2*)&g_att_h[(m0 + 8) * 512 + nn] = make_float2(d[n][2], d[n][3]);
    }
}

// ---------------- gates via tf32 mma, B fragments staged in smem ---------------
__global__ void k_gates(int u) {
    extern __shared__ uint2 bsm[];                   // 8192 uint2 = 64 KB
    int tid = threadIdx.x;
    int lane = tid & 31, wid = tid >> 5;
    int ky = blockIdx.y;
    int mt = blockIdx.x * 8 + wid;

    const uint2* bsrc = (ky == 0)
        ? reinterpret_cast<const uint2*>(g_xemb) + u * 8192
        : reinterpret_cast<const uint2*>(g_xt) + ky * 8192;
#pragma unroll 8
    for (int q = 0; q < 32; q++) bsm[q * 256 + tid] = bsrc[q * 256 + tid];
    __syncthreads();

    float d[4][4];
#pragma unroll
    for (int n = 0; n < 4; n++)
#pragma unroll
        for (int c = 0; c < 4; c++) d[n][c] = 0.0f;

    const uint4* ap = reinterpret_cast<const uint4*>(g_wt) + (mt * 256 + ky * 64) * 32 + lane;
#pragma unroll 4
    for (int kt = 0; kt < 64; kt++) {
        uint4 a = ap[kt * 32];
#pragma unroll
        for (int n = 0; n < 4; n++) {
            uint2 b = bsm[(kt * 4 + n) * 32 + lane];
            mma8(d[n][0], d[n][1], d[n][2], d[n][3], a.x, a.y, a.z, a.w, b.x, b.y);
        }
    }
    int gid = lane >> 2, tig = lane & 3;
    int j0 = mt * 16 + gid;
    float* gp = g_gpart + ky * (G_DIM * 32);
#pragma unroll
    for (int n = 0; n < 4; n++) {
        int bb = n * 8 + 2 * tig;
        *(float2*)&gp[j0 * 32 + bb]       = make_float2(d[n][0], d[n][1]);
        *(float2*)&gp[(j0 + 8) * 32 + bb] = make_float2(d[n][2], d[n][3]);
    }
}

// ---------------- fused LSTM pointwise + proj partial GEMM ---------------------
// grid (8 rowblocks, 8 ky). Each block recomputes the h slice for its ky
// (128 k x 32 b) from gate partials + c_old; blockIdx.x==0 writes c_new.
__global__ void k_proj(const float* __restrict__ Wproj, const float* __restrict__ bias, int u) {
    __shared__ float Wsm[64 * 64];
    __shared__ float xsm[128 * 33];
    int tid = threadIdx.x;
    int lane = tid & 31, w = tid >> 5;
    int ky = blockIdx.y;
    int row0 = blockIdx.x * 64;
    const float* cold = g_c[u & 1];
    float* cnew = g_c[(u + 1) & 1];

    // LSTM pointwise for this ky slice -> xsm[k][b]
#pragma unroll 4
    for (int q = 0; q < 16; q++) {
        int idx = q * 256 + tid;
        int k = idx >> 5, b = idx & 31;
        int ci = ky * 128 + k;
        float gt[4];
#pragma unroll
        for (int gi = 0; gi < 4; gi++) {
            int j = gi * 1024 + ci;
            float s = __ldg(&bias[j]);
            s += g_gpart[j * 32 + b];
            s += g_gpart[131072 + j * 32 + b];
            s += g_gpart[262144 + j * 32 + b];
            s += g_gpart[393216 + j * 32 + b];
            gt[gi] = s;
        }
        float c = cold[ci * 32 + b];
        c = sigf(gt[1]) * c + sigf(gt[0]) * tanhf(gt[2]);
        c = fminf(fmaxf(c, -1.0f), 1.0f);
        float h = sigf(gt[3]) * tanhf(c);
        xsm[k * 33 + b] = h;
        if (blockIdx.x == 0) cnew[ci * 32 + b] = c;
    }

    const float* wsrc = Wproj + ky * 128;
    float4 wr[4];
#pragma unroll
    for (int q = 0; q < 4; q++) {
        int idx = q * 256 + tid; int r = idx >> 4, c = (idx & 15) * 4;
        wr[q] = *(const float4*)&wsrc[(row0 + r) * 1024 + c];
    }
    float acc[8];
#pragma unroll
    for (int r = 0; r < 8; r++) acc[r] = 0.0f;

    for (int sub = 0; sub < 2; sub++) {
        __syncthreads();
#pragma unroll
        for (int q = 0; q < 4; q++) {
            int idx = q * 256 + tid; int r = idx >> 4, c = (idx & 15) * 4;
            *(float4*)&Wsm[r * 64 + c] = wr[q];
        }
        __syncthreads();
        if (sub < 1) {
#pragma unroll
            for (int q = 0; q < 4; q++) {
                int idx = q * 256 + tid; int r = idx >> 4, c = (idx & 15) * 4;
                wr[q] = *(const float4*)&wsrc[(row0 + r) * 1024 + 64 + c];
            }
        }
#pragma unroll 4
        for (int kk = 0; kk < 64; kk += 4) {
            int kb = sub * 64 + kk;
            float x0 = xsm[kb * 33 + lane];
            float x1 = xsm[(kb + 1) * 33 + lane];
            float x2 = xsm[(kb + 2) * 33 + lane];
            float x3 = xsm[(kb + 3) * 33 + lane];
#pragma unroll
            for (int r = 0; r < 8; r++) {
                float4 wv = *(const float4*)&Wsm[(w * 8 + r) * 64 + kk];
                acc[r] += wv.x * x0 + wv.y * x1 + wv.z * x2 + wv.w * x3;
            }
        }
    }
#pragma unroll
    for (int r = 0; r < 8; r++) {
        int j = row0 + w * 8 + r;
        g_ppart[ky * (O_DIM * 32) + j * 32 + lane] = acc[r];
    }
}

// ---------------- state = Wp2s @ p; fused ppart reduce + packed p + out --------
__global__ void k_state(const float* __restrict__ Wp2s, const float* __restrict__ attm,
                        float* __restrict__ out, int u) {
    extern __shared__ float sm[];
    float* xsm = sm;                 // 512*33
    float* Wsm = sm + 512 * 33;      // 64*64
    int tid = threadIdx.x;
    int lane = tid & 31, w = tid >> 5;
    int row0 = blockIdx.x * 64;

    if (blockIdx.x == 0 && tid < 128) g_ctr[tid] = 0;   // reset ctx-reduce counters

#pragma unroll 2
    for (int q = 0; q < 16; q++) {
        int idx = q * 256 + tid; int k = idx >> 3, b = (idx & 7) * 4;
        float4 s = make_float4(0.f, 0.f, 0.f, 0.f);
#pragma unroll
        for (int ky = 0; ky < 8; ky++) {
            float4 v = *(const float4*)&g_ppart[ky * (O_DIM * 32) + k * 32 + b];
            s.x += v.x; s.y += v.y; s.z += v.z; s.w += v.w;
        }
        int base = k * 33 + b;
        xsm[base] = s.x; xsm[base + 1] = s.y; xsm[base + 2] = s.z; xsm[base + 3] = s.w;
        if (blockIdx.x == 0) {
            float sv[4] = {s.x, s.y, s.z, s.w};
            int kt = 192 + (k >> 3);
            int reg = (k >> 2) & 1;
#pragma unroll
            for (int jj = 0; jj < 4; jj++) {
                int bb = b + jj;
                int ln = (bb & 7) * 4 + (k & 3);
                g_xt[((kt * 4 + (bb >> 3)) * 32 + ln) * 2 + reg] = f2tf(sv[jj]);
                out[u * (B_DIM * 1536) + bb * 1536 + k] = sv[jj] * attm[u * 32 + bb];
            }
        }
    }

    float4 wr[4];
#pragma unroll
    for (int q = 0; q < 4; q++) {
        int idx = q * 256 + tid; int r = idx >> 4, c = (idx & 15) * 4;
        wr[q] = *(const float4*)&Wp2s[(row0 + r) * 512 + c];
    }
    float acc[8];
#pragma unroll
    for (int r = 0; r < 8; r++) acc[r] = 0.0f;

    for (int sub = 0; sub < 8; sub++) {
        __syncthreads();
#pragma unroll
        for (int q = 0; q < 4; q++) {
            int idx = q * 256 + tid; int r = idx >> 4, c = (idx & 15) * 4;
            *(float4*)&Wsm[r * 64 + c] = wr[q];
        }
        __syncthreads();
        if (sub < 7) {
#pragma unroll
            for (int q = 0; q < 4; q++) {
                int idx = q * 256 + tid; int r = idx >> 4, c = (idx & 15) * 4;
                wr[q] = *(const float4*)&Wp2s[(row0 + r) * 512 + (sub + 1) * 64 + c];
            }
        }
#pragma unroll 4
        for (int kk = 0; kk < 64; kk += 4) {
            int kb = sub * 64 + kk;
            float x0 = xsm[kb * 33 + lane];
            float x1 = xsm[(kb + 1) * 33 + lane];
            float x2 = xsm[(kb + 2) * 33 + lane];
            float x3 = xsm[(kb + 3) * 33 + lane];
#pragma unroll
            for (int r = 0; r < 8; r++) {
                float4 wv = *(const float4*)&Wsm[(w * 8 + r) * 64 + kk];
                acc[r] += wv.x * x0 + wv.y * x1 + wv.z * x2 + wv.w * x3;
            }
        }
    }
#pragma unroll
    for (int r = 0; r < 8; r++) {
        int m = row0 + w * 8 + r;
        g_state[lane * 512 + m] = acc[r];   // [b][m]
    }
}

// ---------------- attention scalars: one block per t ---------------------------
__global__ void k_scalar(const float* __restrict__ rnn_mask, const float* __restrict__ wv) {
    __shared__ float wvs[512];
    int tid = threadIdx.x;
    int lane = tid & 31, w = tid >> 5;
    if (tid < 512) wvs[tid] = wv[tid];
    __syncthreads();
    int t = blockIdx.x;
#pragma unroll
    for (int rep = 0; rep < 2; rep++) {
        int b = w + rep * 16;
        const float* ah = g_att_h + (t * 32 + b) * 512;
        const float* st = g_state + b * 512;
        float s = 0.0f;
#pragma unroll
        for (int it = 0; it < 16; it++) {
            int m = lane + it * 32;
            s += wvs[m] * fast_tanh(st[m] + ah[m]);
        }
#pragma unroll
        for (int off = 16; off; off >>= 1) s += __shfl_xor_sync(0xffffffffu, s, off);
        if (lane == 0) {
            float bv = (rnn_mask[t * 32 + b] - 1.0f) * 1e10f;
            g_scalar[t * 32 + b] = 1.0f / (1.0f + __expf(-(s + bv)));
        }
    }
}

// ---------------- ctx partials + fused last-block reduce -----------------------
// RACE FIX vs R6/R7: __syncthreads() BEFORE the fence+atomic, so ALL 256
// threads' partial stores are ordered before tid0's __threadfence (a fence
// only orders the calling thread's writes). Partials read via __ldcg (L2).
__global__ void k_ctx(const float* __restrict__ data, const float* __restrict__ attm,
                      float* __restrict__ out, int u) {
    __shared__ float ssm[100];
    __shared__ int isLast;
    int tid = threadIdx.x;
    int t0 = blockIdx.y * 100;
    int idx = blockIdx.x * 256 + tid;          // b*1024 + i
    int b = blockIdx.x >> 2;
    if (tid < 100) ssm[tid] = g_scalar[(t0 + tid) * 32 + b];
    __syncthreads();
    float a0 = 0.0f, a1 = 0.0f;
#pragma unroll 2
    for (int tt = 0; tt < 100; tt += 4) {
        a0 += __ldcs(&data[(t0 + tt + 0) * 32768 + idx]) * ssm[tt + 0];
        a1 += __ldcs(&data[(t0 + tt + 1) * 32768 + idx]) * ssm[tt + 1];
        a0 += __ldcs(&data[(t0 + tt + 2) * 32768 + idx]) * ssm[tt + 2];
        a1 += __ldcs(&data[(t0 + tt + 3) * 32768 + idx]) * ssm[tt + 3];
    }
    g_cpart[blockIdx.y * 32768 + idx] = a0 + a1;

    __syncthreads();                 // order ALL threads' partial stores first
    if (tid == 0) {
        __threadfence();             // now covers the whole block's stores
        int old = atomicAdd(&g_ctr[blockIdx.x], 1);
        isLast = (old == 4);
    }
    __syncthreads();
    if (isLast) {
        __threadfence();
        float s = 0.0f;
#pragma unroll
        for (int p = 0; p < 5; p++) s += __ldcg(&g_cpart[p * 32768 + idx]);
        int bb = idx >> 10, i = idx & 1023;
        int kt = 64 + (i >> 3);
        int ln = (bb & 7) * 4 + (i & 3);
        int reg = (i >> 2) & 1;
        g_xt[((kt * 4 + (bb >> 3)) * 32 + ln) * 2 + reg] = f2tf(s);
        out[u * (B_DIM * 1536) + bb * 1536 + 512 + i] = s * attm[u * 32 + bb];
    }
}

// ---------------- launch --------------------------------------------------------
extern "C" void kernel_launch(void* const* d_in, const int* in_sizes, int n_in,
                              void* d_out, int out_size) {
    const float* data      = (const float*)d_in[0];
    const float* att_mask  = (const float*)d_in[1];
    const int*   att_label = (const int*)  d_in[2];
    const float* rnn_mask  = (const float*)d_in[3];
    const float* embW      = (const float*)d_in[4];
    const float* Wi2h      = (const float*)d_in[5];
    const float* Wp2s      = (const float*)d_in[6];
    const float* wv        = (const float*)d_in[7];
    const float* Wx        = (const float*)d_in[8];
    const float* Wp        = (const float*)d_in[9];
    const float* bias      = (const float*)d_in[10];
    const float* Wproj     = (const float*)d_in[11];
    float* out = (float*)d_out;

    cudaFuncSetAttribute(k_state, cudaFuncAttributeMaxDynamicSharedMemorySize,
                         (512 * 33 + 64 * 64) * 4);
    cudaFuncSetAttribute(k_gates, cudaFuncAttributeMaxDynamicSharedMemorySize, 65536);

    k_wpack<<<32768, 256>>>(Wx, Wp);
    k_dpack<<<64000, 256>>>(data);
    k_bpack<<<2048, 256>>>(Wi2h);
    k_embed<<<6400, 256>>>(att_label, embW);
    k_atth<<<dim3(125, 4), 512>>>();
    k_init<<<256, 256>>>();

    for (int u = 0; u < U_DIM; u++) {
        k_gates<<<dim3(32, 4), 256, 65536>>>(u);
        k_proj<<<dim3(8, 8), 256>>>(Wproj, bias, u);
        k_state<<<8, 256, (512 * 33 + 64 * 64) * 4>>>(Wp2s, att_mask, out, u);
        k_scalar<<<500, 512>>>(rnn_mask, wv);
        k_ctx<<<dim3(128, 5), 256>>>(data, att_mask, out, u);
    }
}

// round 9
// speedup vs baseline: 1.5427x; 1.1160x over previous
#include <cuda_runtime.h>
#include <math.h>
#include <stdint.h>

#define T_DIM 500
#define B_DIM 32
#define U_DIM 100
#define I_DIM 1024
#define E_DIM 512
#define M_DIM 512
#define C_DIM 1024
#define O_DIM 512
#define G_DIM 4096
#define NUM_CLASS 5000

// ---------------- scratch (device globals) -----------------------------------
__device__ __align__(16) uint32_t g_wt[G_DIM / 16 * 2048 / 8 * 32 * 4];  // packed W frags
__device__ __align__(16) uint32_t g_dt[16000 / 16 * 1024 / 8 * 32 * 4]; // packed data frags
__device__ __align__(16) uint32_t g_bt[1024 / 8 * 512 / 8 * 32 * 2];    // packed Wi2h frags
__device__ __align__(16) uint32_t g_xemb[U_DIM * 64 * 4 * 32 * 2];      // packed emb frags
__device__ __align__(16) uint32_t g_xt[256 * 4 * 32 * 2];               // packed x frags (ctx+p)
__device__ float g_att_h[T_DIM * B_DIM * M_DIM];     // [t*32+b][m]
__device__ float g_gpart[4 * G_DIM * B_DIM];         // [ky][j][b]
__device__ float g_ppart[8 * O_DIM * B_DIM];         // [ky][r][b]
__device__ float g_c[2][C_DIM * B_DIM];              // double-buffered cell state
__device__ float g_state[B_DIM * M_DIM];             // [b][m]
__device__ float g_cpart[5 * B_DIM * I_DIM];         // [chunk][b*1024+i]
__device__ int   g_ctr[32];                          // per-b ctx-reduce counters
__device__ unsigned g_barA;                          // global barrier counter (kernel A)

__device__ __forceinline__ float fast_tanh(float x) {
    float y; asm("tanh.approx.f32 %0, %1;" : "=f"(y) : "f"(x)); return y;
}
__device__ __forceinline__ float sigf(float x) { return 1.0f / (1.0f + expf(-x)); }
__device__ __forceinline__ uint32_t f2tf(float v) {
    uint32_t r; asm("cvt.rna.tf32.f32 %0, %1;" : "=r"(r) : "f"(v)); return r;
}
__device__ __forceinline__ void mma8(float& d0, float& d1, float& d2, float& d3,
                                     uint32_t a0, uint32_t a1, uint32_t a2, uint32_t a3,
                                     uint32_t b0, uint32_t b1) {
    asm("mma.sync.aligned.m16n8k8.row.col.f32.tf32.tf32.f32 "
        "{%0,%1,%2,%3},{%4,%5,%6,%7},{%8,%9},{%0,%1,%2,%3};"
        : "+f"(d0), "+f"(d1), "+f"(d2), "+f"(d3)
        : "r"(a0), "r"(a1), "r"(a2), "r"(a3), "r"(b0), "r"(b1));
}

// global barrier helpers: all 128 blocks of kernel A are co-resident
// (grid 128 <= 148 SMs, 1 block/SM), so spinning is deadlock-free.
__device__ __forceinline__ void gbar_arrive() {
    __syncthreads();
    if (threadIdx.x == 0) { __threadfence(); atomicAdd(&g_barA, 1u); }
}
__device__ __forceinline__ void gbar(unsigned target) {
    __syncthreads();
    if (threadIdx.x == 0) {
        __threadfence();
        atomicAdd(&g_barA, 1u);
        while (atomicAdd(&g_barA, 0u) < target) __nanosleep(64);
    }
    __syncthreads();
}

// ---------------- pack W = [Wx | Wp] into A-fragment layout -------------------
__global__ void k_wpack(const float* __restrict__ Wx, const float* __restrict__ Wp) {
    int idx = blockIdx.x * 256 + threadIdx.x;        // 8,388,608
    int r = idx & 3, lane = (idx >> 2) & 31, kt = (idx >> 7) & 255, mt = idx >> 15;
    int j = mt * 16 + (lane >> 2) + (r & 1) * 8;
    int k = kt * 8 + (lane & 3) + (r >> 1) * 4;
    float v = (k < 1536) ? Wx[j * 1536 + k] : Wp[j * 512 + (k - 1536)];
    g_wt[idx] = f2tf(v);
}

// ---------------- pack data into A-fragment layout ----------------------------
__global__ void k_dpack(const float* __restrict__ data) {
    int idx = blockIdx.x * 256 + threadIdx.x;        // 16,384,000
    int r = idx & 3, lane = (idx >> 2) & 31, kt = (idx >> 7) & 127, mt = idx >> 14;
    int m = mt * 16 + (lane >> 2) + (r & 1) * 8;
    int k = kt * 8 + (lane & 3) + (r >> 1) * 4;
    g_dt[idx] = f2tf(data[m * 1024 + k]);
}

// ---------------- pack Wi2h into B-fragment layout ----------------------------
__global__ void k_bpack(const float* __restrict__ Wi2h) {
    int idx = blockIdx.x * 256 + threadIdx.x;        // 524,288
    int r = idx & 1, lane = (idx >> 1) & 31, nt = (idx >> 6) & 63, kt = idx >> 12;
    int k = kt * 8 + (lane & 3) + r * 4;
    int n = nt * 8 + (lane >> 2);
    g_bt[idx] = f2tf(Wi2h[n * 1024 + k]);
}

// ---------------- embedding -> packed B fragments per u ------------------------
__global__ void k_embed(const int* __restrict__ label, const float* __restrict__ embW) {
    int idx = blockIdx.x * 256 + threadIdx.x;        // 1,638,400
    int r = idx & 1, lane = (idx >> 1) & 31, nt = (idx >> 6) & 3, kt = (idx >> 8) & 63, u = idx >> 14;
    int e = kt * 8 + (lane & 3) + r * 4;
    int b = nt * 8 + (lane >> 2);
    int lab = (u == 0) ? (NUM_CLASS - 2) : label[(u - 1) * B_DIM + b];
    float v = 0.0f;
    if (lab >= 0) v = embW[lab * E_DIM + e];
    g_xemb[idx] = f2tf(v);
}

// ---------------- init: zero c buf0, packed x, barrier/counters ----------------
__global__ void k_init() {
    int idx = blockIdx.x * 256 + threadIdx.x;        // 65536
    if (idx < C_DIM * B_DIM) g_c[0][idx] = 0.0f;
    if (idx < 65536) g_xt[idx] = 0u;
    if (idx < 32) g_ctr[idx] = 0;
    if (idx == 0) g_barA = 0u;
}

// ---------------- att_h via tf32 mma -------------------------------------------
__global__ void __launch_bounds__(512) k_atth(void) {
    int tid = threadIdx.x;
    int lane = tid & 31, wid = tid >> 5;
    int wm = wid & 7, wn = wid >> 3;
    int mt = blockIdx.x * 8 + wm;
    int ntb = blockIdx.y * 16 + wn * 8;

    float d[8][4];
#pragma unroll
    for (int n = 0; n < 8; n++)
#pragma unroll
        for (int c = 0; c < 4; c++) d[n][c] = 0.0f;

    const uint4* ap = reinterpret_cast<const uint4*>(g_dt) + (mt * 128) * 32 + lane;
    const uint2* bp = reinterpret_cast<const uint2*>(g_bt) + ntb * 32 + lane;
#pragma unroll 2
    for (int kt = 0; kt < 128; kt++) {
        uint4 a = ap[kt * 32];
#pragma unroll
        for (int n = 0; n < 8; n++) {
            uint2 b = bp[(kt * 64 + n) * 32];
            mma8(d[n][0], d[n][1], d[n][2], d[n][3], a.x, a.y, a.z, a.w, b.x, b.y);
        }
    }
    int gid = lane >> 2, tig = lane & 3;
    int m0 = mt * 16 + gid;
#pragma unroll
    for (int n = 0; n < 8; n++) {
        int nn = (ntb + n) * 8 + 2 * tig;
        *(float2*)&g_att_h[m0 * 512 + nn]       = make_float2(d[n][0], d[n][1]);
        *(float2*)&g_att_h[(m0 + 8) * 512 + nn] = make_float2(d[n][2], d[n][3]);
    }
}

// ================ kernel A: gates -> (bar) -> lstm+proj -> (bar) -> state ======
// grid 128 blocks x 256 threads, 84KB dyn smem (1 block/SM; all wave-1 resident)
__global__ void __launch_bounds__(256) k_step(const float* __restrict__ Wproj,
                                              const float* __restrict__ bias,
                                              const float* __restrict__ Wp2s,
                                              const float* __restrict__ attm,
                                              float* __restrict__ out, int u) {
    extern __shared__ char smA[];
    int tid = threadIdx.x;
    int lane = tid & 31, wid = tid >> 5;
    int blk = blockIdx.x;

    // ---------- phase 1: gates (all 128 blocks) ----------
    {
        uint2* bsm = (uint2*)smA;                    // 64 KB
        int x = blk & 31, ky = blk >> 5;
        int mt = x * 8 + wid;
        const uint2* bsrc = (ky == 0)
            ? reinterpret_cast<const uint2*>(g_xemb) + u * 8192
            : reinterpret_cast<const uint2*>(g_xt) + ky * 8192;
#pragma unroll 8
        for (int q = 0; q < 32; q++) bsm[q * 256 + tid] = bsrc[q * 256 + tid];
        if (blk == 0 && tid < 32) g_ctr[tid] = 0;    // reset B's counters
        __syncthreads();

        float d[4][4];
#pragma unroll
        for (int n = 0; n < 4; n++)
#pragma unroll
            for (int c = 0; c < 4; c++) d[n][c] = 0.0f;

        const uint4* ap = reinterpret_cast<const uint4*>(g_wt) + (mt * 256 + ky * 64) * 32 + lane;
#pragma unroll 4
        for (int kt = 0; kt < 64; kt++) {
            uint4 a = ap[kt * 32];
#pragma unroll
            for (int n = 0; n < 4; n++) {
                uint2 b = bsm[(kt * 4 + n) * 32 + lane];
                mma8(d[n][0], d[n][1], d[n][2], d[n][3], a.x, a.y, a.z, a.w, b.x, b.y);
            }
        }
        int gid = lane >> 2, tig = lane & 3;
        int j0 = mt * 16 + gid;
        float* gp = g_gpart + ky * (G_DIM * 32);
#pragma unroll
        for (int n = 0; n < 4; n++) {
            int bb = n * 8 + 2 * tig;
            *(float2*)&gp[j0 * 32 + bb]       = make_float2(d[n][0], d[n][1]);
            *(float2*)&gp[(j0 + 8) * 32 + bb] = make_float2(d[n][2], d[n][3]);
        }
    }
    gbar(128);

    // ---------- phase 2: fused LSTM + proj partial (blocks 0..63) ----------
    if (blk < 64) {
        float* Wsm = (float*)smA;                    // 16 KB
        float* xsm = (float*)(smA + 16384);          // 16.9 KB
        int ky = blk >> 3;
        int row0 = (blk & 7) * 64;
        const float* cold = g_c[u & 1];
        float* cnew = g_c[(u + 1) & 1];

#pragma unroll 4
        for (int q = 0; q < 16; q++) {
            int idx = q * 256 + tid;
            int k = idx >> 5, b = idx & 31;
            int ci = ky * 128 + k;
            float gt[4];
#pragma unroll
            for (int gi = 0; gi < 4; gi++) {
                int j = gi * 1024 + ci;
                float s = __ldg(&bias[j]);
                s += __ldcg(&g_gpart[j * 32 + b]);
                s += __ldcg(&g_gpart[131072 + j * 32 + b]);
                s += __ldcg(&g_gpart[262144 + j * 32 + b]);
                s += __ldcg(&g_gpart[393216 + j * 32 + b]);
                gt[gi] = s;
            }
            float c = cold[ci * 32 + b];
            c = sigf(gt[1]) * c + sigf(gt[0]) * tanhf(gt[2]);
            c = fminf(fmaxf(c, -1.0f), 1.0f);
            float h = sigf(gt[3]) * tanhf(c);
            xsm[k * 33 + b] = h;
            if ((blk & 7) == 0) cnew[ci * 32 + b] = c;
        }

        const float* wsrc = Wproj + ky * 128;
        float4 wr[4];
#pragma unroll
        for (int q = 0; q < 4; q++) {
            int idx = q * 256 + tid; int r = idx >> 4, c = (idx & 15) * 4;
            wr[q] = *(const float4*)&wsrc[(row0 + r) * 1024 + c];
        }
        float acc[8];
#pragma unroll
        for (int r = 0; r < 8; r++) acc[r] = 0.0f;

        for (int sub = 0; sub < 2; sub++) {
            __syncthreads();
#pragma unroll
            for (int q = 0; q < 4; q++) {
                int idx = q * 256 + tid; int r = idx >> 4, c = (idx & 15) * 4;
                *(float4*)&Wsm[r * 64 + c] = wr[q];
            }
            __syncthreads();
            if (sub < 1) {
#pragma unroll
                for (int q = 0; q < 4; q++) {
                    int idx = q * 256 + tid; int r = idx >> 4, c = (idx & 15) * 4;
                    wr[q] = *(const float4*)&wsrc[(row0 + r) * 1024 + 64 + c];
                }
            }
#pragma unroll 4
            for (int kk = 0; kk < 64; kk += 4) {
                int kb = sub * 64 + kk;
                float x0 = xsm[kb * 33 + lane];
                float x1 = xsm[(kb + 1) * 33 + lane];
                float x2 = xsm[(kb + 2) * 33 + lane];
                float x3 = xsm[(kb + 3) * 33 + lane];
#pragma unroll
                for (int r = 0; r < 8; r++) {
                    float4 wv4 = *(const float4*)&Wsm[(wid * 8 + r) * 64 + kk];
                    acc[r] += wv4.x * x0 + wv4.y * x1 + wv4.z * x2 + wv4.w * x3;
                }
            }
        }
#pragma unroll
        for (int r = 0; r < 8; r++) {
            int j = row0 + wid * 8 + r;
            g_ppart[ky * (O_DIM * 32) + j * 32 + lane] = acc[r];
        }
    }

    // ---------- barrier 2 + phase 3: state (blocks 0..7) ----------
    if (blk >= 8) { gbar_arrive(); return; }
    gbar(256);
    {
        float* xsm = (float*)smA;                    // 512*33*4 = 67.6 KB
        float* Wsm = (float*)(smA + 67584);          // 16 KB
        int row0 = blk * 64;

#pragma unroll 2
        for (int q = 0; q < 16; q++) {
            int idx = q * 256 + tid; int k = idx >> 3, b = (idx & 7) * 4;
            float4 s = make_float4(0.f, 0.f, 0.f, 0.f);
#pragma unroll
            for (int ky = 0; ky < 8; ky++) {
                float4 v = __ldcg((const float4*)&g_ppart[ky * (O_DIM * 32) + k * 32 + b]);
                s.x += v.x; s.y += v.y; s.z += v.z; s.w += v.w;
            }
            int base = k * 33 + b;
            xsm[base] = s.x; xsm[base + 1] = s.y; xsm[base + 2] = s.z; xsm[base + 3] = s.w;
            if (blk == 0) {
                float sv[4] = {s.x, s.y, s.z, s.w};
                int kt = 192 + (k >> 3);
                int reg = (k >> 2) & 1;
#pragma unroll
                for (int jj = 0; jj < 4; jj++) {
                    int bb = b + jj;
                    int ln = (bb & 7) * 4 + (k & 3);
                    g_xt[((kt * 4 + (bb >> 3)) * 32 + ln) * 2 + reg] = f2tf(sv[jj]);
                    out[u * (B_DIM * 1536) + bb * 1536 + k] = sv[jj] * attm[u * 32 + bb];
                }
            }
        }

        float4 wr[4];
#pragma unroll
        for (int q = 0; q < 4; q++) {
            int idx = q * 256 + tid; int r = idx >> 4, c = (idx & 15) * 4;
            wr[q] = *(const float4*)&Wp2s[(row0 + r) * 512 + c];
        }
        float acc[8];
#pragma unroll
        for (int r = 0; r < 8; r++) acc[r] = 0.0f;

        for (int sub = 0; sub < 8; sub++) {
            __syncthreads();
#pragma unroll
            for (int q = 0; q < 4; q++) {
                int idx = q * 256 + tid; int r = idx >> 4, c = (idx & 15) * 4;
                *(float4*)&Wsm[r * 64 + c] = wr[q];
            }
            __syncthreads();
            if (sub < 7) {
#pragma unroll
                for (int q = 0; q < 4; q++) {
                    int idx = q * 256 + tid; int r = idx >> 4, c = (idx & 15) * 4;
                    wr[q] = *(const float4*)&Wp2s[(row0 + r) * 512 + (sub + 1) * 64 + c];
                }
            }
#pragma unroll 4
            for (int kk = 0; kk < 64; kk += 4) {
                int kb = sub * 64 + kk;
                float x0 = xsm[kb * 33 + lane];
                float x1 = xsm[(kb + 1) * 33 + lane];
                float x2 = xsm[(kb + 2) * 33 + lane];
                float x3 = xsm[(kb + 3) * 33 + lane];
#pragma unroll
                for (int r = 0; r < 8; r++) {
                    float4 wv4 = *(const float4*)&Wsm[(wid * 8 + r) * 64 + kk];
                    acc[r] += wv4.x * x0 + wv4.y * x1 + wv4.z * x2 + wv4.w * x3;
                }
            }
        }
#pragma unroll
        for (int r = 0; r < 8; r++) {
            int m = row0 + wid * 8 + r;
            g_state[lane * 512 + m] = acc[r];        // [b][m]
        }
    }
}

// ================ kernel B: attention scalars + ctx + last-block reduce ========
// grid (32 b, 5 t-chunks) x 512 threads
__global__ void __launch_bounds__(512) k_att(const float* __restrict__ data,
                                             const float* __restrict__ rnn_mask,
                                             const float* __restrict__ wv,
                                             const float* __restrict__ attm,
                                             float* __restrict__ out, int u) {
    __shared__ float ssm[100];
    __shared__ float stt[512];
    __shared__ float wvs[512];
    __shared__ int isLast;
    int tid = threadIdx.x;
    int lane = tid & 31, w = tid >> 5;
    int b = blockIdx.x, chunk = blockIdx.y;
    int t0 = chunk * 100;

    if (b == 0 && chunk == 0 && tid == 0) g_barA = 0u;  // reset A's barrier

    stt[tid] = g_state[b * 512 + tid];
    wvs[tid] = wv[tid];
    __syncthreads();

    // scalar phase: each warp covers t = t0+w, t0+w+16, ...
    for (int t = t0 + w; t < t0 + 100; t += 16) {
        const float* ah = g_att_h + (t * 32 + b) * 512;
        float s = 0.0f;
#pragma unroll
        for (int it = 0; it < 16; it++) {
            int m = lane + it * 32;
            s += wvs[m] * fast_tanh(stt[m] + ah[m]);
        }
#pragma unroll
        for (int off = 16; off; off >>= 1) s += __shfl_xor_sync(0xffffffffu, s, off);
        if (lane == 0) {
            float bv = (rnn_mask[t * 32 + b] - 1.0f) * 1e10f;
            ssm[t - t0] = 1.0f / (1.0f + __expf(-(s + bv)));
        }
    }
    __syncthreads();

    // ctx phase: stream 100 t x 1024 i (float2 per thread)
    const float* dbase = data + b * 1024 + 2 * tid;
    float ax = 0.0f, ay = 0.0f;
    for (int tt = 0; tt < 100; tt += 10) {
        float2 v[10];
#pragma unroll
        for (int j = 0; j < 10; j++)
            v[j] = __ldcs((const float2*)(dbase + (size_t)(t0 + tt + j) * 32768));
#pragma unroll
        for (int j = 0; j < 10; j++) {
            float sc = ssm[tt + j];
            ax += v[j].x * sc; ay += v[j].y * sc;
        }
    }
    *(float2*)&g_cpart[chunk * 32768 + b * 1024 + 2 * tid] = make_float2(ax, ay);

    __syncthreads();                 // order ALL threads' partial stores first
    if (tid == 0) {
        __threadfence();
        int old = atomicAdd(&g_ctr[b], 1);
        isLast = (old == 4);
    }
    __syncthreads();
    if (isLast) {
        __threadfence();
#pragma unroll
        for (int half = 0; half < 2; half++) {
            int i = tid + half * 512;
            float s = 0.0f;
#pragma unroll
            for (int p = 0; p < 5; p++) s += __ldcg(&g_cpart[p * 32768 + b * 1024 + i]);
            int kt = 64 + (i >> 3);
            int ln = (b & 7) * 4 + (i & 3);
            int reg = (i >> 2) & 1;
            g_xt[((kt * 4 + (b >> 3)) * 32 + ln) * 2 + reg] = f2tf(s);
            out[u * (B_DIM * 1536) + b * 1536 + 512 + i] = s * attm[u * 32 + b];
        }
    }
}

// ---------------- launch --------------------------------------------------------
extern "C" void kernel_launch(void* const* d_in, const int* in_sizes, int n_in,
                              void* d_out, int out_size) {
    const float* data      = (const float*)d_in[0];
    const float* att_mask  = (const float*)d_in[1];
    const int*   att_label = (const int*)  d_in[2];
    const float* rnn_mask  = (const float*)d_in[3];
    const float* embW      = (const float*)d_in[4];
    const float* Wi2h      = (const float*)d_in[5];
    const float* Wp2s      = (const float*)d_in[6];
    const float* wv        = (const float*)d_in[7];
    const float* Wx        = (const float*)d_in[8];
    const float* Wp        = (const float*)d_in[9];
    const float* bias      = (const float*)d_in[10];
    const float* Wproj     = (const float*)d_in[11];
    float* out = (float*)d_out;

    cudaFuncSetAttribute(k_step, cudaFuncAttributeMaxDynamicSharedMemorySize, 83968);

    k_wpack<<<32768, 256>>>(Wx, Wp);
    k_dpack<<<64000, 256>>>(data);
    k_bpack<<<2048, 256>>>(Wi2h);
    k_embed<<<6400, 256>>>(att_label, embW);
    k_atth<<<dim3(125, 4), 512>>>();
    k_init<<<256, 256>>>();

    for (int u = 0; u < U_DIM; u++) {
        k_step<<<128, 256, 83968>>>(Wproj, bias, Wp2s, att_mask, out, u);
        k_att<<<dim3(32, 5), 512>>>(data, rnn_mask, wv, att_mask, out, u);
    }
}

// round 10
// speedup vs baseline: 1.8867x; 1.2230x over previous
#include <cuda_runtime.h>
#include <math.h>
#include <stdint.h>

#define T_DIM 500
#define B_DIM 32
#define U_DIM 100
#define I_DIM 1024
#define E_DIM 512
#define M_DIM 512
#define C_DIM 1024
#define O_DIM 512
#define G_DIM 4096
#define NUM_CLASS 5000

// ---------------- scratch (device globals) -----------------------------------
__device__ __align__(16) uint32_t g_wt[G_DIM / 16 * 2048 / 8 * 32 * 4];  // packed W frags
__device__ __align__(16) uint32_t g_dt[16000 / 16 * 1024 / 8 * 32 * 4]; // packed data frags
__device__ __align__(16) uint32_t g_bt[1024 / 8 * 512 / 8 * 32 * 2];    // packed Wi2h frags
__device__ __align__(16) uint32_t g_xemb[U_DIM * 64 * 4 * 32 * 2];      // packed emb frags
__device__ __align__(16) uint32_t g_xt[256 * 4 * 32 * 2];               // packed x frags (ctx+p)
__device__ float g_att_h[T_DIM * B_DIM * M_DIM];     // [t*32+b][m]
__device__ float g_gpart[4 * G_DIM * B_DIM];         // [ky][j][b]
__device__ float g_ppart[8 * O_DIM * B_DIM];         // [ky][r][b]
__device__ float g_spart[16 * M_DIM * B_DIM];        // [ksp][m][b]
__device__ float g_c[2][C_DIM * B_DIM];              // double-buffered cell state
__device__ float g_cpart[4 * B_DIM * I_DIM];         // [chunk][b*1024+i]
__device__ int   g_ctr[32];                          // per-b ctx counters (monotonic)
__device__ unsigned g_barA;                          // global barrier (monotonic)

__device__ __forceinline__ float fast_tanh(float x) {
    float y; asm("tanh.approx.f32 %0, %1;" : "=f"(y) : "f"(x)); return y;
}
__device__ __forceinline__ float sigf(float x) { return 1.0f / (1.0f + expf(-x)); }
__device__ __forceinline__ uint32_t f2tf(float v) {
    uint32_t r; asm("cvt.rna.tf32.f32 %0, %1;" : "=r"(r) : "f"(v)); return r;
}
__device__ __forceinline__ void mma8(float& d0, float& d1, float& d2, float& d3,
                                     uint32_t a0, uint32_t a1, uint32_t a2, uint32_t a3,
                                     uint32_t b0, uint32_t b1) {
    asm("mma.sync.aligned.m16n8k8.row.col.f32.tf32.tf32.f32 "
        "{%0,%1,%2,%3},{%4,%5,%6,%7},{%8,%9},{%0,%1,%2,%3};"
        : "+f"(d0), "+f"(d1), "+f"(d2), "+f"(d3)
        : "r"(a0), "r"(a1), "r"(a2), "r"(a3), "r"(b0), "r"(b1));
}

// monotonic global barrier; all 128 blocks co-resident (grid 128 <= 148 SMs)
__device__ __forceinline__ void gbar(unsigned target) {
    __syncthreads();
    if (threadIdx.x == 0) {
        __threadfence();
        atomicAdd(&g_barA, 1u);
        while (atomicAdd(&g_barA, 0u) < target) __nanosleep(32);
        __threadfence();
    }
    __syncthreads();
}

// ---------------- pack W = [Wx | Wp] into A-fragment layout -------------------
__global__ void k_wpack(const float* __restrict__ Wx, const float* __restrict__ Wp) {
    int idx = blockIdx.x * 256 + threadIdx.x;        // 8,388,608
    int r = idx & 3, lane = (idx >> 2) & 31, kt = (idx >> 7) & 255, mt = idx >> 15;
    int j = mt * 16 + (lane >> 2) + (r & 1) * 8;
    int k = kt * 8 + (lane & 3) + (r >> 1) * 4;
    float v = (k < 1536) ? Wx[j * 1536 + k] : Wp[j * 512 + (k - 1536)];
    g_wt[idx] = f2tf(v);
}

// ---------------- pack data into A-fragment layout ----------------------------
__global__ void k_dpack(const float* __restrict__ data) {
    int idx = blockIdx.x * 256 + threadIdx.x;        // 16,384,000
    int r = idx & 3, lane = (idx >> 2) & 31, kt = (idx >> 7) & 127, mt = idx >> 14;
    int m = mt * 16 + (lane >> 2) + (r & 1) * 8;
    int k = kt * 8 + (lane & 3) + (r >> 1) * 4;
    g_dt[idx] = f2tf(data[m * 1024 + k]);
}

// ---------------- pack Wi2h into B-fragment layout ----------------------------
__global__ void k_bpack(const float* __restrict__ Wi2h) {
    int idx = blockIdx.x * 256 + threadIdx.x;        // 524,288
    int r = idx & 1, lane = (idx >> 1) & 31, nt = (idx >> 6) & 63, kt = idx >> 12;
    int k = kt * 8 + (lane & 3) + r * 4;
    int n = nt * 8 + (lane >> 2);
    g_bt[idx] = f2tf(Wi2h[n * 1024 + k]);
}

// ---------------- embedding -> packed B fragments per u ------------------------
__global__ void k_embed(const int* __restrict__ label, const float* __restrict__ embW) {
    int idx = blockIdx.x * 256 + threadIdx.x;        // 1,638,400
    int r = idx & 1, lane = (idx >> 1) & 31, nt = (idx >> 6) & 3, kt = (idx >> 8) & 63, u = idx >> 14;
    int e = kt * 8 + (lane & 3) + r * 4;
    int b = nt * 8 + (lane >> 2);
    int lab = (u == 0) ? (NUM_CLASS - 2) : label[(u - 1) * B_DIM + b];
    float v = 0.0f;
    if (lab >= 0) v = embW[lab * E_DIM + e];
    g_xemb[idx] = f2tf(v);
}

// ---------------- init: zero c buf0, packed x, barrier + counters --------------
__global__ void k_init() {
    int idx = blockIdx.x * 256 + threadIdx.x;        // 65536
    if (idx < C_DIM * B_DIM) g_c[0][idx] = 0.0f;
    if (idx < 65536) g_xt[idx] = 0u;
    if (idx < 32) g_ctr[idx] = 0;
    if (idx == 0) g_barA = 0u;
}

// ---------------- att_h via tf32 mma -------------------------------------------
__global__ void __launch_bounds__(512) k_atth(void) {
    int tid = threadIdx.x;
    int lane = tid & 31, wid = tid >> 5;
    int wm = wid & 7, wn = wid >> 3;
    int mt = blockIdx.x * 8 + wm;
    int ntb = blockIdx.y * 16 + wn * 8;

    float d[8][4];
#pragma unroll
    for (int n = 0; n < 8; n++)
#pragma unroll
        for (int c = 0; c < 4; c++) d[n][c] = 0.0f;

    const uint4* ap = reinterpret_cast<const uint4*>(g_dt) + (mt * 128) * 32 + lane;
    const uint2* bp = reinterpret_cast<const uint2*>(g_bt) + ntb * 32 + lane;
#pragma unroll 2
    for (int kt = 0; kt < 128; kt++) {
        uint4 a = ap[kt * 32];
#pragma unroll
        for (int n = 0; n < 8; n++) {
            uint2 b = bp[(kt * 64 + n) * 32];
            mma8(d[n][0], d[n][1], d[n][2], d[n][3], a.x, a.y, a.z, a.w, b.x, b.y);
        }
    }
    int gid = lane >> 2, tig = lane & 3;
    int m0 = mt * 16 + gid;
#pragma unroll
    for (int n = 0; n < 8; n++) {
        int nn = (ntb + n) * 8 + 2 * tig;
        *(float2*)&g_att_h[m0 * 512 + nn]       = make_float2(d[n][0], d[n][1]);
        *(float2*)&g_att_h[(m0 + 8) * 512 + nn] = make_float2(d[n][2], d[n][3]);
    }
}

// ================ persistent mega-kernel: all 100 steps =========================
// 128 blocks x 256 threads, 64KB dyn smem -> 1 block/SM, all wave-1 resident.
// All mutable cross-block buffers read via __ldcg (no per-launch L1 flush here).
__global__ void __launch_bounds__(256) k_mega(const float* __restrict__ Wproj,
                                              const float* __restrict__ bias,
                                              const float* __restrict__ Wp2s,
                                              const float* __restrict__ attm,
                                              const float* __restrict__ data,
                                              const float* __restrict__ rnn_mask,
                                              const float* __restrict__ wv,
                                              float* __restrict__ out) {
    extern __shared__ char smA[];
    __shared__ int isLast;
    int tid = threadIdx.x;
    int lane = tid & 31, wid = tid >> 5;
    int blk = blockIdx.x;

#pragma unroll 1
    for (int u = 0; u < U_DIM; u++) {
        unsigned base = (unsigned)u * 512u;

        // ---------- phase 1: gates mma (all 128 blocks: 32 x-blocks x 4 ky) ----
        {
            uint2* bsm = (uint2*)smA;                // 64 KB
            int x = blk & 31, ky = blk >> 5;
            int mt = x * 8 + wid;
            const uint2* bsrc = (ky == 0)
                ? reinterpret_cast<const uint2*>(g_xemb) + u * 8192
                : reinterpret_cast<const uint2*>(g_xt) + ky * 8192;
#pragma unroll 8
            for (int q = 0; q < 32; q++) bsm[q * 256 + tid] = __ldcg(&bsrc[q * 256 + tid]);
            __syncthreads();

            float d[4][4];
#pragma unroll
            for (int n = 0; n < 4; n++)
#pragma unroll
                for (int c = 0; c < 4; c++) d[n][c] = 0.0f;

            const uint4* ap = reinterpret_cast<const uint4*>(g_wt) + (mt * 256 + ky * 64) * 32 + lane;
#pragma unroll 4
            for (int kt = 0; kt < 64; kt++) {
                uint4 a = ap[kt * 32];
#pragma unroll
                for (int n = 0; n < 4; n++) {
                    uint2 b = bsm[(kt * 4 + n) * 32 + lane];
                    mma8(d[n][0], d[n][1], d[n][2], d[n][3], a.x, a.y, a.z, a.w, b.x, b.y);
                }
            }
            int gid = lane >> 2, tig = lane & 3;
            int j0 = mt * 16 + gid;
            float* gp = g_gpart + ky * (G_DIM * 32);
#pragma unroll
            for (int n = 0; n < 4; n++) {
                int bb = n * 8 + 2 * tig;
                *(float2*)&gp[j0 * 32 + bb]       = make_float2(d[n][0], d[n][1]);
                *(float2*)&gp[(j0 + 8) * 32 + bb] = make_float2(d[n][2], d[n][3]);
            }
        }
        gbar(base + 128);

        // ---------- phase 2: fused LSTM + proj partials (blocks 0..63) ---------
        if (blk < 64) {
            float* Wsm = (float*)smA;                // 16 KB
            float* xsm = (float*)(smA + 16384);      // 128*33*4
            int ky = blk >> 3;
            int row0 = (blk & 7) * 64;
            const float* cold = g_c[u & 1];
            float* cnew = g_c[(u + 1) & 1];

#pragma unroll 4
            for (int q = 0; q < 16; q++) {
                int idx = q * 256 + tid;
                int k = idx >> 5, b = idx & 31;
                int ci = ky * 128 + k;
                float gt[4];
#pragma unroll
                for (int gi = 0; gi < 4; gi++) {
                    int j = gi * 1024 + ci;
                    float s = __ldg(&bias[j]);
                    s += __ldcg(&g_gpart[j * 32 + b]);
                    s += __ldcg(&g_gpart[131072 + j * 32 + b]);
                    s += __ldcg(&g_gpart[262144 + j * 32 + b]);
                    s += __ldcg(&g_gpart[393216 + j * 32 + b]);
                    gt[gi] = s;
                }
                float c = __ldcg(&cold[ci * 32 + b]);
                c = sigf(gt[1]) * c + sigf(gt[0]) * tanhf(gt[2]);
                c = fminf(fmaxf(c, -1.0f), 1.0f);
                float h = sigf(gt[3]) * tanhf(c);
                xsm[k * 33 + b] = h;
                if ((blk & 7) == 0) cnew[ci * 32 + b] = c;
            }

            const float* wsrc = Wproj + ky * 128;
            float4 wr[4];
#pragma unroll
            for (int q = 0; q < 4; q++) {
                int idx = q * 256 + tid; int r = idx >> 4, c = (idx & 15) * 4;
                wr[q] = *(const float4*)&wsrc[(row0 + r) * 1024 + c];
            }
            float acc[8];
#pragma unroll
            for (int r = 0; r < 8; r++) acc[r] = 0.0f;

            for (int sub = 0; sub < 2; sub++) {
                __syncthreads();
#pragma unroll
                for (int q = 0; q < 4; q++) {
                    int idx = q * 256 + tid; int r = idx >> 4, c = (idx & 15) * 4;
                    *(float4*)&Wsm[r * 64 + c] = wr[q];
                }
                __syncthreads();
                if (sub < 1) {
#pragma unroll
                    for (int q = 0; q < 4; q++) {
                        int idx = q * 256 + tid; int r = idx >> 4, c = (idx & 15) * 4;
                        wr[q] = *(const float4*)&wsrc[(row0 + r) * 1024 + 64 + c];
                    }
                }
#pragma unroll 4
                for (int kk = 0; kk < 64; kk += 4) {
                    int kb = sub * 64 + kk;
                    float x0 = xsm[kb * 33 + lane];
                    float x1 = xsm[(kb + 1) * 33 + lane];
                    float x2 = xsm[(kb + 2) * 33 + lane];
                    float x3 = xsm[(kb + 3) * 33 + lane];
#pragma unroll
                    for (int r = 0; r < 8; r++) {
                        float4 wv4 = *(const float4*)&Wsm[(wid * 8 + r) * 64 + kk];
                        acc[r] += wv4.x * x0 + wv4.y * x1 + wv4.z * x2 + wv4.w * x3;
                    }
                }
            }
#pragma unroll
            for (int r = 0; r < 8; r++) {
                int j = row0 + wid * 8 + r;
                g_ppart[ky * (O_DIM * 32) + j * 32 + lane] = acc[r];
            }
        }
        gbar(base + 256);

        // ---------- phase 3: state partials (128 blocks: 8 mrow x 16 ksplit) ---
        {
            float* psm  = (float*)smA;               // 32*33 floats
            float* Wsm3 = (float*)(smA + 4224);      // 64*33 floats
            int mrow = blk >> 4, ksp = blk & 15;
            int k0 = ksp * 32;

#pragma unroll
            for (int q = 0; q < 4; q++) {
                int idx = q * 256 + tid; int rl = idx >> 5, b = idx & 31;
                float s = 0.0f;
#pragma unroll
                for (int ky = 0; ky < 8; ky++)
                    s += __ldcg(&g_ppart[ky * (O_DIM * 32) + (k0 + rl) * 32 + b]);
                psm[rl * 33 + b] = s;
                if (mrow == 0) {                     // packed p + masked lstmp out
                    int k = k0 + rl;
                    int kt = 192 + (k >> 3), reg = (k >> 2) & 1, ln = (b & 7) * 4 + (k & 3);
                    g_xt[((kt * 4 + (b >> 3)) * 32 + ln) * 2 + reg] = f2tf(s);
                    out[u * (B_DIM * 1536) + b * 1536 + k] = s * attm[u * 32 + b];
                }
            }
#pragma unroll
            for (int q = 0; q < 8; q++) {
                int idx = q * 256 + tid; int r = idx >> 5, c = idx & 31;
                Wsm3[r * 33 + c] = Wp2s[(mrow * 64 + r) * 512 + k0 + c];
            }
            __syncthreads();

            float acc[8];
#pragma unroll
            for (int r = 0; r < 8; r++) acc[r] = 0.0f;
#pragma unroll 8
            for (int rl = 0; rl < 32; rl++) {
                float x = psm[rl * 33 + lane];
#pragma unroll
                for (int r = 0; r < 8; r++)
                    acc[r] += Wsm3[(wid * 8 + r) * 33 + rl] * x;
            }
#pragma unroll
            for (int r = 0; r < 8; r++) {
                int m = mrow * 64 + wid * 8 + r;
                g_spart[ksp * (M_DIM * 32) + m * 32 + lane] = acc[r];
            }
        }
        gbar(base + 384);

        // ---------- phase 4: scalars + ctx (128 blocks: 32 b x 4 chunks) -------
        {
            float* stt = (float*)smA;                // 512
            float* wvs = (float*)(smA + 2048);       // 512
            float* ssm = (float*)(smA + 4096);       // 125
            int b = blk >> 2, chunk = blk & 3;
            int t0 = chunk * 125;

#pragma unroll
            for (int q = 0; q < 2; q++) {            // state[b][m] from 16 partials
                int m = q * 256 + tid;
                float s = 0.0f;
#pragma unroll
                for (int ksp = 0; ksp < 16; ksp++)
                    s += __ldcg(&g_spart[ksp * (M_DIM * 32) + m * 32 + b]);
                stt[m] = s;
            }
#pragma unroll
            for (int m = tid; m < 512; m += 256) wvs[m] = wv[m];
            __syncthreads();

            for (int t = t0 + wid; t < t0 + 125; t += 8) {
                const float* ah = g_att_h + (t * 32 + b) * 512;
                float s = 0.0f;
#pragma unroll
                for (int it = 0; it < 16; it++) {
                    int m = lane + it * 32;
                    s += wvs[m] * fast_tanh(stt[m] + ah[m]);
                }
#pragma unroll
                for (int off = 16; off; off >>= 1) s += __shfl_xor_sync(0xffffffffu, s, off);
                if (lane == 0) {
                    float bv = (rnn_mask[t * 32 + b] - 1.0f) * 1e10f;
                    ssm[t - t0] = 1.0f / (1.0f + __expf(-(s + bv)));
                }
            }
            __syncthreads();

            const float* dbase = data + (size_t)t0 * 32768 + b * 1024 + tid * 4;
            float4 a4 = make_float4(0.f, 0.f, 0.f, 0.f);
            for (int tt = 0; tt < 125; tt += 5) {
                float4 v[5];
#pragma unroll
                for (int j = 0; j < 5; j++)
                    v[j] = __ldcs((const float4*)(dbase + (size_t)(tt + j) * 32768));
#pragma unroll
                for (int j = 0; j < 5; j++) {
                    float sc = ssm[tt + j];
                    a4.x += v[j].x * sc; a4.y += v[j].y * sc;
                    a4.z += v[j].z * sc; a4.w += v[j].w * sc;
                }
            }
            *(float4*)&g_cpart[chunk * 32768 + b * 1024 + tid * 4] = a4;

            __syncthreads();                         // all stores before fence
            if (tid == 0) {
                __threadfence();
                int old = atomicAdd(&g_ctr[b], 1);
                isLast = (old == u * 4 + 3);         // monotonic per replay
            }
            __syncthreads();
            if (isLast) {
                __threadfence();
                float4 s4 = make_float4(0.f, 0.f, 0.f, 0.f);
#pragma unroll
                for (int p = 0; p < 4; p++) {
                    float4 v = __ldcg((const float4*)&g_cpart[p * 32768 + b * 1024 + tid * 4]);
                    s4.x += v.x; s4.y += v.y; s4.z += v.z; s4.w += v.w;
                }
                float sv[4] = {s4.x, s4.y, s4.z, s4.w};
#pragma unroll
                for (int c = 0; c < 4; c++) {
                    int i = tid * 4 + c;
                    int kt = 64 + (i >> 3), ln = (b & 7) * 4 + (i & 3), reg = (i >> 2) & 1;
                    g_xt[((kt * 4 + (b >> 3)) * 32 + ln) * 2 + reg] = f2tf(sv[c]);
                    out[u * (B_DIM * 1536) + b * 1536 + 512 + i] = sv[c] * attm[u * 32 + b];
                }
            }
        }
        gbar(base + 512);   // g_xt complete before next step's gates
    }
}

// ---------------- launch --------------------------------------------------------
extern "C" void kernel_launch(void* const* d_in, const int* in_sizes, int n_in,
                              void* d_out, int out_size) {
    const float* data      = (const float*)d_in[0];
    const float* att_mask  = (const float*)d_in[1];
    const int*   att_label = (const int*)  d_in[2];
    const float* rnn_mask  = (const float*)d_in[3];
    const float* embW      = (const float*)d_in[4];
    const float* Wi2h      = (const float*)d_in[5];
    const float* Wp2s      = (const float*)d_in[6];
    const float* wv        = (const float*)d_in[7];
    const float* Wx        = (const float*)d_in[8];
    const float* Wp        = (const float*)d_in[9];
    const float* bias      = (const float*)d_in[10];
    const float* Wproj     = (const float*)d_in[11];
    float* out = (float*)d_out;

    cudaFuncSetAttribute(k_mega, cudaFuncAttributeMaxDynamicSharedMemorySize, 65536);

    k_wpack<<<32768, 256>>>(Wx, Wp);
    k_dpack<<<64000, 256>>>(data);
    k_bpack<<<2048, 256>>>(Wi2h);
    k_embed<<<6400, 256>>>(att_label, embW);
    k_atth<<<dim3(125, 4), 512>>>();
    k_init<<<256, 256>>>();

    k_mega<<<128, 256, 65536>>>(Wproj, bias, Wp2s, att_mask, data,
                                rnn_mask, wv, out);
}